// round 1
// baseline (speedup 1.0000x reference)
#include <cuda_runtime.h>
#include <math.h>

// Problem constants
#define B_  2
#define T_  2048
#define D_  2048
#define E_  3072          // D + 2*KV_DIM
#define KV_ 512           // NUM_KV_HEADS * HEAD_DIM
#define HD_ 64            // head dim
#define NH_ 32            // query heads
#define BT_ 4096          // B*T

// Scratch (allocation-free rule: static __device__ arrays)
__device__ float g_qkv[BT_ * E_];    // [b*T+t][3072] = q(2048) | k(512) | v(512)
__device__ float g_attn[BT_ * D_];   // attention output, (b,t,h,dh) flattened

// ---------------------------------------------------------------------------
// SGEMM: C[M,N] = A[M,K] * W[K,N], all row-major. M%128==0, N%128==0, K%16==0.
// 128x128 tile, BK=16, 256 threads, 8x8 per-thread register tile.
// ---------------------------------------------------------------------------
__global__ void __launch_bounds__(256) sgemm_kernel(
    const float* __restrict__ A, const float* __restrict__ W,
    float* __restrict__ C, int M, int N, int K)
{
    __shared__ float As[16][128];   // transposed: As[k][m]
    __shared__ float Bs[16][128];   // Bs[k][n]

    const int tid  = threadIdx.x;
    const int row0 = blockIdx.y * 128;
    const int col0 = blockIdx.x * 128;
    const int tx = tid & 15;
    const int ty = tid >> 4;
    const int m0 = ty * 8;
    const int n0 = tx * 8;

    float acc[8][8];
#pragma unroll
    for (int i = 0; i < 8; i++)
#pragma unroll
        for (int j = 0; j < 8; j++) acc[i][j] = 0.f;

    for (int kb = 0; kb < K; kb += 16) {
        // Load A tile: 128 rows x 16 cols = 512 float4s, 2 per thread, transpose into As
#pragma unroll
        for (int l = 0; l < 2; l++) {
            int idx = tid + l * 256;
            int r   = idx >> 2;          // 0..127
            int c4  = (idx & 3) * 4;     // 0,4,8,12
            float4 v = *(const float4*)(A + (long)(row0 + r) * K + kb + c4);
            As[c4 + 0][r] = v.x;
            As[c4 + 1][r] = v.y;
            As[c4 + 2][r] = v.z;
            As[c4 + 3][r] = v.w;
        }
        // Load B tile: 16 rows x 128 cols = 512 float4s, coalesced
#pragma unroll
        for (int l = 0; l < 2; l++) {
            int idx = tid + l * 256;
            int r   = idx >> 5;          // 0..15
            int c4  = (idx & 31) * 4;    // 0..124
            *(float4*)(&Bs[r][c4]) = *(const float4*)(W + (long)(kb + r) * N + col0 + c4);
        }
        __syncthreads();

#pragma unroll
        for (int kk = 0; kk < 16; kk++) {
            float a[8], b[8];
            *(float4*)(a)     = *(float4*)(&As[kk][m0]);
            *(float4*)(a + 4) = *(float4*)(&As[kk][m0 + 4]);
            *(float4*)(b)     = *(float4*)(&Bs[kk][n0]);
            *(float4*)(b + 4) = *(float4*)(&Bs[kk][n0 + 4]);
#pragma unroll
            for (int i = 0; i < 8; i++)
#pragma unroll
                for (int j = 0; j < 8; j++)
                    acc[i][j] = fmaf(a[i], b[j], acc[i][j]);
        }
        __syncthreads();
    }

#pragma unroll
    for (int i = 0; i < 8; i++) {
#pragma unroll
        for (int j = 0; j < 8; j += 4) {
            float4 v = make_float4(acc[i][j], acc[i][j + 1], acc[i][j + 2], acc[i][j + 3]);
            *(float4*)(C + (long)(row0 + m0 + i) * N + col0 + n0 + j) = v;
        }
    }
}

// ---------------------------------------------------------------------------
// RoPE in place on q (32 heads) and k (8 heads) parts of qkv.
// out[i]    = u[i]*cos[i]    - u[i+32]*sin[i]
// out[i+32] = u[i+32]*cos[i+32] + u[i]*sin[i+32]
// ---------------------------------------------------------------------------
__global__ void rope_kernel(const float* __restrict__ sinb, const float* __restrict__ cosb)
{
    const int bt = blockIdx.x;           // 0..4095
    const int t  = bt & (T_ - 1);
    float* base = g_qkv + (long)bt * E_;

    for (int p = threadIdx.x; p < 40 * 32; p += blockDim.x) {
        int hh = p >> 5;                 // 0..39 (32 q heads, then 8 k heads)
        int i  = p & 31;
        int off = (hh < 32) ? hh * HD_ : D_ + (hh - 32) * HD_;
        float u1 = base[off + i];
        float u2 = base[off + i + 32];
        float c1 = cosb[t * HD_ + i],      s1 = sinb[t * HD_ + i];
        float c2 = cosb[t * HD_ + i + 32], s2 = sinb[t * HD_ + i + 32];
        base[off + i]      = u1 * c1 - u2 * s1;
        base[off + i + 32] = u2 * c2 + u1 * s2;
    }
}

// ---------------------------------------------------------------------------
// Flash attention, causal, GQA (q head h uses kv head h>>2).
// Block: 64 q-rows x full head dim (64). 256 threads, 4x4 register tile.
// Dynamic smem: Qs,Ks,Vs,Ss each 64x68 floats + alpha[64] + l[64].
// ---------------------------------------------------------------------------
#define APAD 68
extern __shared__ float attn_smem[];

__global__ void __launch_bounds__(256) attn_kernel(float* __restrict__ out)
{
    float* Qs      = attn_smem;                 // [64][APAD]
    float* Ks      = Qs + 64 * APAD;
    float* Vs      = Ks + 64 * APAD;
    float* Ss      = Vs + 64 * APAD;
    float* alpha_s = Ss + 64 * APAD;            // [64]
    float* l_s     = alpha_s + 64;              // [64]

    const int qb  = blockIdx.x;                 // 0..31 (q tile)
    const int h   = blockIdx.y;                 // 0..31
    const int b   = blockIdx.z;                 // 0..1
    const int tid = threadIdx.x;
    const int tx  = tid & 15;
    const int ty  = tid >> 4;
    const int q0  = qb * 64;
    const float scale = 0.125f;                 // 64^-0.5

    const float* Qg = g_qkv + (long)(b * T_) * E_ + h * HD_;
    const float* Kg = g_qkv + (long)(b * T_) * E_ + D_ + (h >> 2) * HD_;
    const float* Vg = Kg + KV_;

    // Load Q tile (64 rows x 64 floats)
    for (int idx = tid; idx < 64 * 16; idx += 256) {
        int r  = idx >> 4;
        int c4 = (idx & 15) * 4;
        *(float4*)(&Qs[r * APAD + c4]) = *(const float4*)(Qg + (long)(q0 + r) * E_ + c4);
    }

    float m = -INFINITY, l = 0.f;
    float acc[4][4];
#pragma unroll
    for (int i = 0; i < 4; i++)
#pragma unroll
        for (int j = 0; j < 4; j++) acc[i][j] = 0.f;

    for (int jb = 0; jb <= qb; jb++) {
        const int k0 = jb * 64;
        __syncthreads();   // protect Ks/Vs/Ss of previous iteration
        for (int idx = tid; idx < 64 * 16; idx += 256) {
            int r  = idx >> 4;
            int c4 = (idx & 15) * 4;
            *(float4*)(&Ks[r * APAD + c4]) = *(const float4*)(Kg + (long)(k0 + r) * E_ + c4);
            *(float4*)(&Vs[r * APAD + c4]) = *(const float4*)(Vg + (long)(k0 + r) * E_ + c4);
        }
        __syncthreads();

        // S = Q * K^T (register 4x4)
        float s[4][4];
#pragma unroll
        for (int i = 0; i < 4; i++)
#pragma unroll
            for (int j = 0; j < 4; j++) s[i][j] = 0.f;

#pragma unroll 8
        for (int kk = 0; kk < 64; kk++) {
            float qf[4], kf[4];
#pragma unroll
            for (int i = 0; i < 4; i++) qf[i] = Qs[(ty * 4 + i) * APAD + kk];
#pragma unroll
            for (int j = 0; j < 4; j++) kf[j] = Ks[(tx * 4 + j) * APAD + kk];
#pragma unroll
            for (int i = 0; i < 4; i++)
#pragma unroll
                for (int j = 0; j < 4; j++)
                    s[i][j] = fmaf(qf[i], kf[j], s[i][j]);
        }

        const bool diag = (jb == qb);
#pragma unroll
        for (int i = 0; i < 4; i++) {
#pragma unroll
            for (int j = 0; j < 4; j++) {
                float v = s[i][j] * scale;
                if (diag && (k0 + tx * 4 + j) > (q0 + ty * 4 + i)) v = -INFINITY;
                Ss[(ty * 4 + i) * APAD + tx * 4 + j] = v;
            }
        }
        __syncthreads();

        // Online softmax stats: one thread per row (tid < 64 owns row tid)
        if (tid < 64) {
            float rmax = -INFINITY;
            for (int c = 0; c < 64; c++) rmax = fmaxf(rmax, Ss[tid * APAD + c]);
            float mn = fmaxf(m, rmax);
            float a  = __expf(m - mn);
            float sum = 0.f;
            for (int c = 0; c < 64; c++) {
                float p = __expf(Ss[tid * APAD + c] - mn);
                Ss[tid * APAD + c] = p;
                sum += p;
            }
            l = l * a + sum;
            m = mn;
            alpha_s[tid] = a;
        }
        __syncthreads();

        // acc = acc*alpha + P * V
        float al[4];
#pragma unroll
        for (int i = 0; i < 4; i++) al[i] = alpha_s[ty * 4 + i];
#pragma unroll
        for (int i = 0; i < 4; i++)
#pragma unroll
            for (int j = 0; j < 4; j++) acc[i][j] *= al[i];

#pragma unroll 8
        for (int kk = 0; kk < 64; kk++) {
            float pf[4], vf[4];
#pragma unroll
            for (int i = 0; i < 4; i++) pf[i] = Ss[(ty * 4 + i) * APAD + kk];
            *(float4*)vf = *(float4*)(&Vs[kk * APAD + tx * 4]);
#pragma unroll
            for (int i = 0; i < 4; i++)
#pragma unroll
                for (int j = 0; j < 4; j++)
                    acc[i][j] = fmaf(pf[i], vf[j], acc[i][j]);
        }
    }

    if (tid < 64) l_s[tid] = l;
    __syncthreads();

    float inv[4];
#pragma unroll
    for (int i = 0; i < 4; i++) inv[i] = 1.f / l_s[ty * 4 + i];

    float* outg = out + (long)(b * T_) * D_ + h * HD_;
#pragma unroll
    for (int i = 0; i < 4; i++) {
#pragma unroll
        for (int j = 0; j < 4; j++) {
            outg[(long)(q0 + ty * 4 + i) * D_ + tx * 4 + j] = acc[i][j] * inv[i];
        }
    }
}

// ---------------------------------------------------------------------------
// Launch
// ---------------------------------------------------------------------------
extern "C" void kernel_launch(void* const* d_in, const int* in_sizes, int n_in,
                              void* d_out, int out_size)
{
    const float* x     = (const float*)d_in[0];   // (2,2048,2048)
    const float* sinb  = (const float*)d_in[1];   // (2048,64)
    const float* cosb  = (const float*)d_in[2];   // (2048,64)
    const float* w_qkv = (const float*)d_in[3];   // (2048,3072)
    const float* w_out = (const float*)d_in[4];   // (2048,2048)
    float* out = (float*)d_out;                   // (2,2048,2048)

    float* qkv_ptr;
    float* attn_ptr;
    cudaGetSymbolAddress((void**)&qkv_ptr, g_qkv);
    cudaGetSymbolAddress((void**)&attn_ptr, g_attn);

    // Attention kernel needs > 48KB dynamic smem
    const int attn_smem_bytes = (4 * 64 * APAD + 128) * (int)sizeof(float);
    cudaFuncSetAttribute(attn_kernel, cudaFuncAttributeMaxDynamicSharedMemorySize,
                         attn_smem_bytes);

    // 1) QKV projection: (4096,2048) @ (2048,3072)
    {
        dim3 grid(E_ / 128, BT_ / 128);
        sgemm_kernel<<<grid, 256>>>(x, w_qkv, qkv_ptr, BT_, E_, D_);
    }
    // 2) RoPE in place on q/k
    rope_kernel<<<BT_, 256>>>(sinb, cosb);

    // 3) Causal GQA flash attention
    {
        dim3 grid(T_ / 64, NH_, B_);
        attn_kernel<<<grid, 256, attn_smem_bytes>>>(attn_ptr);
    }
    // 4) Output projection: (4096,2048) @ (2048,2048)
    {
        dim3 grid(D_ / 128, BT_ / 128);
        sgemm_kernel<<<grid, 256>>>(attn_ptr, w_out, out, BT_, D_, D_);
    }
}

// round 3
// speedup vs baseline: 2.2580x; 2.2580x over previous
#include <cuda_runtime.h>
#include <cuda_bf16.h>
#include <math.h>

// Problem constants
#define B_  2
#define T_  2048
#define D_  2048
#define E_  3072          // D + 2*KV_DIM
#define KV_ 512
#define HD_ 64
#define NH_ 32
#define BT_ 4096          // B*T

#define LOG2E 1.4426950408889634f

// Scratch (static __device__ arrays; allocation-free rule)
__device__ float g_qkv[BT_ * E_];            // fp32 qkv
__device__ float g_attn[BT_ * D_];           // attention output fp32
__device__ __nv_bfloat16 g_wqkv_h[E_ * D_];  // W_qkv^T [N=3072][K=2048] hi
__device__ __nv_bfloat16 g_wqkv_l[E_ * D_];  // lo
__device__ __nv_bfloat16 g_wout_h[D_ * D_];  // W_out^T [2048][2048] hi
__device__ __nv_bfloat16 g_wout_l[D_ * D_];  // lo

// ---------------------------------------------------------------------------
// helpers
// ---------------------------------------------------------------------------
__device__ __forceinline__ unsigned pack2(float x, float y) {
    __nv_bfloat162 h = __floats2bfloat162_rn(x, y);   // .x in low half
    return *(unsigned*)&h;
}
__device__ __forceinline__ float resid(float x) {
    return x - __bfloat162float(__float2bfloat16_rn(x));
}
__device__ __forceinline__ void mma16816(float c[4], const unsigned a[4], const unsigned b[2]) {
    asm volatile(
        "mma.sync.aligned.m16n8k16.row.col.f32.bf16.bf16.f32 "
        "{%0,%1,%2,%3},{%4,%5,%6,%7},{%8,%9},{%0,%1,%2,%3};\n"
        : "+f"(c[0]), "+f"(c[1]), "+f"(c[2]), "+f"(c[3])
        : "r"(a[0]), "r"(a[1]), "r"(a[2]), "r"(a[3]), "r"(b[0]), "r"(b[1]));
}
__device__ __forceinline__ void cp16(void* dst_smem, const void* src) {
    unsigned d = (unsigned)__cvta_generic_to_shared(dst_smem);
    asm volatile("cp.async.cg.shared.global [%0], [%1], 16;\n" :: "r"(d), "l"(src));
}
__device__ __forceinline__ void cp_commit() { asm volatile("cp.async.commit_group;\n" ::: "memory"); }
__device__ __forceinline__ void cp_wait0()  { asm volatile("cp.async.wait_group 0;\n" ::: "memory"); }
__device__ __forceinline__ void ldmx4t(unsigned r[4], const void* p) {
    unsigned a = (unsigned)__cvta_generic_to_shared(p);
    asm volatile("ldmatrix.sync.aligned.m8n8.x4.trans.shared.b16 {%0,%1,%2,%3},[%4];\n"
                 : "=r"(r[0]), "=r"(r[1]), "=r"(r[2]), "=r"(r[3]) : "r"(a));
}

// ---------------------------------------------------------------------------
// Weight split+transpose: W[K][N] fp32 -> Wt_hi/Wt_lo [N][K] bf16
// ---------------------------------------------------------------------------
__global__ void wsplit_kernel(const float* __restrict__ W,
                              __nv_bfloat16* __restrict__ Oh,
                              __nv_bfloat16* __restrict__ Ol, int K, int N)
{
    __shared__ float t[32][33];
    int n0 = blockIdx.x * 32, k0 = blockIdx.y * 32;
    for (int i = threadIdx.y; i < 32; i += 8)
        t[i][threadIdx.x] = W[(long)(k0 + i) * N + n0 + threadIdx.x];
    __syncthreads();
    for (int i = threadIdx.y; i < 32; i += 8) {
        float v = t[threadIdx.x][i];               // W[k0+tx][n0+i]
        long o = (long)(n0 + i) * K + k0 + threadIdx.x;
        __nv_bfloat16 h = __float2bfloat16_rn(v);
        Oh[o] = h;
        Ol[o] = __float2bfloat16_rn(v - __bfloat162float(h));
    }
}

// ---------------------------------------------------------------------------
// GEMM (bf16x3 tensor-core): C[M,N] = A[M,K](fp32) * W[K,N]
// W pre-split/transposed to [N][K] bf16 hi/lo. 128x128x32 tiles, 256 threads,
// warptile 32x64, double-buffered smem, cp.async for W, fp32->bf16 split of A
// on the fly. Smem rows padded to 40 halves (conflict-free fragment LDS).
// ---------------------------------------------------------------------------
#define GSTR 20   // u32 words per smem row (40 halves: 32 data + 8 pad)
#define STAGE_U32 (4 * 128 * GSTR)   // Ah,Al,Bh,Bl per stage (40960 B)

__global__ void __launch_bounds__(256) gemm_bf16x3(
    const float* __restrict__ A,
    const __nv_bfloat16* __restrict__ Bh_g, const __nv_bfloat16* __restrict__ Bl_g,
    float* __restrict__ C, int M, int N, int K)
{
    extern __shared__ __align__(16) unsigned smem[];
    const int tid = threadIdx.x, lane = tid & 31, warp = tid >> 5;
    const int row0 = blockIdx.y * 128, col0 = blockIdx.x * 128;
    const int m0 = (warp >> 1) * 32, n0w = (warp & 1) * 64;
    const int rw = lane >> 2, cw = lane & 3;

    unsigned* Ah[2]; unsigned* Al[2]; unsigned* Bh[2]; unsigned* Bl[2];
#pragma unroll
    for (int s = 0; s < 2; s++) {
        unsigned* base = smem + s * STAGE_U32;
        Ah[s] = base;
        Al[s] = base + 128 * GSTR;
        Bh[s] = base + 2 * 128 * GSTR;
        Bl[s] = base + 3 * 128 * GSTR;
    }

    float acc[2][8][4];
#pragma unroll
    for (int mt = 0; mt < 2; mt++)
#pragma unroll
        for (int nt = 0; nt < 8; nt++)
#pragma unroll
            for (int e = 0; e < 4; e++) acc[mt][nt][e] = 0.f;

    float4 areg[4];
    const int nk = K >> 5;

    // ---- prologue: tile 0
#pragma unroll
    for (int l2 = 0; l2 < 4; l2++) {
        int idx = tid + l2 * 256, r = idx >> 3, c = (idx & 7) << 2;
        areg[l2] = *(const float4*)(A + (long)(row0 + r) * K + c);
    }
#pragma unroll
    for (int l2 = 0; l2 < 4; l2++) {
        int idx = tid + l2 * 256, mat = idx >> 9, r = (idx >> 2) & 127, c8 = (idx & 3) << 3;
        const __nv_bfloat16* src = (mat ? Bl_g : Bh_g) + (long)(col0 + r) * K + c8;
        unsigned* dst = (mat ? Bl[0] : Bh[0]) + r * GSTR + (c8 >> 1);
        cp16(dst, src);
    }
    cp_commit();
#pragma unroll
    for (int l2 = 0; l2 < 4; l2++) {
        int idx = tid + l2 * 256, r = idx >> 3, c = (idx & 7) << 2;
        int w = r * GSTR + (c >> 1);
        float4 v = areg[l2];
        Ah[0][w]     = pack2(v.x, v.y);
        Ah[0][w + 1] = pack2(v.z, v.w);
        Al[0][w]     = pack2(resid(v.x), resid(v.y));
        Al[0][w + 1] = pack2(resid(v.z), resid(v.w));
    }
    cp_wait0();
    __syncthreads();

    int st = 0;
    for (int kb = 0; kb < nk; kb++) {
        const bool pre = (kb + 1) < nk;
        if (pre) {
#pragma unroll
            for (int l2 = 0; l2 < 4; l2++) {
                int idx = tid + l2 * 256, r = idx >> 3, c = (idx & 7) << 2;
                areg[l2] = *(const float4*)(A + (long)(row0 + r) * K + (kb + 1) * 32 + c);
            }
#pragma unroll
            for (int l2 = 0; l2 < 4; l2++) {
                int idx = tid + l2 * 256, mat = idx >> 9, r = (idx >> 2) & 127, c8 = (idx & 3) << 3;
                const __nv_bfloat16* src = (mat ? Bl_g : Bh_g) + (long)(col0 + r) * K + (kb + 1) * 32 + c8;
                unsigned* dst = (mat ? Bl[st ^ 1] : Bh[st ^ 1]) + r * GSTR + (c8 >> 1);
                cp16(dst, src);
            }
            cp_commit();
        }

        // ---- MMA on stage st
#pragma unroll
        for (int s = 0; s < 2; s++) {
            unsigned ah[2][4], al[2][4];
#pragma unroll
            for (int mt = 0; mt < 2; mt++) {
                int base = (m0 + mt * 16 + rw) * GSTR + s * 8 + cw;
                ah[mt][0] = Ah[st][base];
                ah[mt][1] = Ah[st][base + 8 * GSTR];
                ah[mt][2] = Ah[st][base + 4];
                ah[mt][3] = Ah[st][base + 8 * GSTR + 4];
                al[mt][0] = Al[st][base];
                al[mt][1] = Al[st][base + 8 * GSTR];
                al[mt][2] = Al[st][base + 4];
                al[mt][3] = Al[st][base + 8 * GSTR + 4];
            }
#pragma unroll
            for (int nt = 0; nt < 8; nt++) {
                int bb = (n0w + nt * 8 + rw) * GSTR + s * 8 + cw;
                unsigned bh[2] = { Bh[st][bb], Bh[st][bb + 4] };
                unsigned bl[2] = { Bl[st][bb], Bl[st][bb + 4] };
#pragma unroll
                for (int mt = 0; mt < 2; mt++) {
                    mma16816(acc[mt][nt], ah[mt], bh);
                    mma16816(acc[mt][nt], ah[mt], bl);
                    mma16816(acc[mt][nt], al[mt], bh);
                }
            }
        }

        if (pre) {
#pragma unroll
            for (int l2 = 0; l2 < 4; l2++) {
                int idx = tid + l2 * 256, r = idx >> 3, c = (idx & 7) << 2;
                int w = r * GSTR + (c >> 1);
                float4 v = areg[l2];
                Ah[st ^ 1][w]     = pack2(v.x, v.y);
                Ah[st ^ 1][w + 1] = pack2(v.z, v.w);
                Al[st ^ 1][w]     = pack2(resid(v.x), resid(v.y));
                Al[st ^ 1][w + 1] = pack2(resid(v.z), resid(v.w));
            }
            cp_wait0();
        }
        __syncthreads();
        st ^= 1;
    }

    // ---- epilogue
#pragma unroll
    for (int mt = 0; mt < 2; mt++) {
#pragma unroll
        for (int nt = 0; nt < 8; nt++) {
            int row = row0 + m0 + mt * 16 + rw;
            int col = col0 + n0w + nt * 8 + cw * 2;
            *(float2*)(C + (long)row * N + col)       = make_float2(acc[mt][nt][0], acc[mt][nt][1]);
            *(float2*)(C + (long)(row + 8) * N + col) = make_float2(acc[mt][nt][2], acc[mt][nt][3]);
        }
    }
}

// ---------------------------------------------------------------------------
// RoPE in place on q/k parts of qkv (fp32)
// ---------------------------------------------------------------------------
__global__ void rope_kernel(const float* __restrict__ sinb, const float* __restrict__ cosb)
{
    const int bt = blockIdx.x;
    const int t  = bt & (T_ - 1);
    float* base = g_qkv + (long)bt * E_;
    for (int p = threadIdx.x; p < 40 * 32; p += blockDim.x) {
        int hh = p >> 5, i = p & 31;
        int off = (hh < 32) ? hh * HD_ : D_ + (hh - 32) * HD_;
        float u1 = base[off + i];
        float u2 = base[off + i + 32];
        float c1 = cosb[t * HD_ + i],      s1 = sinb[t * HD_ + i];
        float c2 = cosb[t * HD_ + i + 32], s2 = sinb[t * HD_ + i + 32];
        base[off + i]      = u1 * c1 - u2 * s1;
        base[off + i + 32] = u2 * c2 + u1 * s2;
    }
}

// ---------------------------------------------------------------------------
// Flash attention (causal, GQA) on tensor cores. 128 threads (4 warps), each
// warp owns 16 q-rows of a 64-row q tile. K/V tiles 64x64. Q,K,V,P in bf16
// hi/lo split (3 mmas per product). Softmax fully in registers.
// Smem rows: 72 halves (36 words).
// ---------------------------------------------------------------------------
#define ASTR 36

__global__ void __launch_bounds__(128) attn_mma(float* __restrict__ out)
{
    extern __shared__ __align__(16) unsigned asmem[];
    unsigned* Qh = asmem;
    unsigned* Ql = Qh + 64 * ASTR;
    unsigned* Kh = Ql + 64 * ASTR;
    unsigned* Kl = Kh + 64 * ASTR;
    unsigned* Vh = Kl + 64 * ASTR;
    unsigned* Vl = Vh + 64 * ASTR;

    const int tid = threadIdx.x, lane = tid & 31, warp = tid >> 5;
    const int qb = blockIdx.x, h = blockIdx.y, b = blockIdx.z;
    const int q0 = qb * 64;
    const int rw = lane >> 2, cw = lane & 3;
    const int qrow = warp * 16 + rw;

    const float* Qg = g_qkv + (long)(b * T_) * E_ + h * HD_;
    const float* Kg = g_qkv + (long)(b * T_) * E_ + D_ + (h >> 2) * HD_;
    const float* Vg = Kg + KV_;

    // load Q tile (split)
#pragma unroll
    for (int l2 = 0; l2 < 8; l2++) {
        int idx = tid + l2 * 128, r = idx >> 4, c4 = (idx & 15) << 2;
        float4 v = *(const float4*)(Qg + (long)(q0 + r) * E_ + c4);
        int w = r * ASTR + (c4 >> 1);
        Qh[w]     = pack2(v.x, v.y);
        Qh[w + 1] = pack2(v.z, v.w);
        Ql[w]     = pack2(resid(v.x), resid(v.y));
        Ql[w + 1] = pack2(resid(v.z), resid(v.w));
    }

    float O[8][4];
#pragma unroll
    for (int nt = 0; nt < 8; nt++)
#pragma unroll
        for (int e = 0; e < 4; e++) O[nt][e] = 0.f;
    float m0 = -INFINITY, m1 = -INFINITY, l0 = 0.f, l1 = 0.f;

    for (int jb = 0; jb <= qb; jb++) {
        const int k0 = jb * 64;
        __syncthreads();    // also protects Q on first iter, K/V reuse later
#pragma unroll
        for (int l2 = 0; l2 < 8; l2++) {
            int idx = tid + l2 * 128, r = idx >> 4, c4 = (idx & 15) << 2;
            int w = r * ASTR + (c4 >> 1);
            float4 kv = *(const float4*)(Kg + (long)(k0 + r) * E_ + c4);
            Kh[w]     = pack2(kv.x, kv.y);
            Kh[w + 1] = pack2(kv.z, kv.w);
            Kl[w]     = pack2(resid(kv.x), resid(kv.y));
            Kl[w + 1] = pack2(resid(kv.z), resid(kv.w));
            float4 vv = *(const float4*)(Vg + (long)(k0 + r) * E_ + c4);
            Vh[w]     = pack2(vv.x, vv.y);
            Vh[w + 1] = pack2(vv.z, vv.w);
            Vl[w]     = pack2(resid(vv.x), resid(vv.y));
            Vl[w + 1] = pack2(resid(vv.z), resid(vv.w));
        }
        __syncthreads();

        // S = Q K^T
        float S[8][4];
#pragma unroll
        for (int nt = 0; nt < 8; nt++)
#pragma unroll
            for (int e = 0; e < 4; e++) S[nt][e] = 0.f;

#pragma unroll
        for (int s = 0; s < 4; s++) {
            unsigned qh[4], ql[4];
            int qb_ = qrow * ASTR + s * 8 + cw;
            qh[0] = Qh[qb_];            qh[1] = Qh[qb_ + 8 * ASTR];
            qh[2] = Qh[qb_ + 4];        qh[3] = Qh[qb_ + 8 * ASTR + 4];
            ql[0] = Ql[qb_];            ql[1] = Ql[qb_ + 8 * ASTR];
            ql[2] = Ql[qb_ + 4];        ql[3] = Ql[qb_ + 8 * ASTR + 4];
#pragma unroll
            for (int nt = 0; nt < 8; nt++) {
                int kb_ = (nt * 8 + rw) * ASTR + s * 8 + cw;
                unsigned kh[2] = { Kh[kb_], Kh[kb_ + 4] };
                unsigned kl[2] = { Kl[kb_], Kl[kb_ + 4] };
                mma16816(S[nt], qh, kh);
                mma16816(S[nt], qh, kl);
                mma16816(S[nt], ql, kh);
            }
        }

        // scale + causal mask
        const float sc = 0.125f;
        if (jb == qb) {
#pragma unroll
            for (int nt = 0; nt < 8; nt++)
#pragma unroll
                for (int e = 0; e < 4; e++) {
                    int r = q0 + warp * 16 + rw + ((e >= 2) ? 8 : 0);
                    int c = k0 + nt * 8 + cw * 2 + (e & 1);
                    S[nt][e] = (c <= r) ? S[nt][e] * sc : -1e30f;
                }
        } else {
#pragma unroll
            for (int nt = 0; nt < 8; nt++)
#pragma unroll
                for (int e = 0; e < 4; e++) S[nt][e] *= sc;
        }

        // online softmax (rows T/4 and T/4+8)
        float mx0 = -INFINITY, mx1 = -INFINITY;
#pragma unroll
        for (int nt = 0; nt < 8; nt++) {
            mx0 = fmaxf(mx0, fmaxf(S[nt][0], S[nt][1]));
            mx1 = fmaxf(mx1, fmaxf(S[nt][2], S[nt][3]));
        }
        mx0 = fmaxf(mx0, __shfl_xor_sync(0xffffffff, mx0, 1));
        mx0 = fmaxf(mx0, __shfl_xor_sync(0xffffffff, mx0, 2));
        mx1 = fmaxf(mx1, __shfl_xor_sync(0xffffffff, mx1, 1));
        mx1 = fmaxf(mx1, __shfl_xor_sync(0xffffffff, mx1, 2));
        float mn0 = fmaxf(m0, mx0), mn1 = fmaxf(m1, mx1);
        float a0 = exp2f((m0 - mn0) * LOG2E), a1 = exp2f((m1 - mn1) * LOG2E);
        m0 = mn0; m1 = mn1;
        float sum0 = 0.f, sum1 = 0.f;
#pragma unroll
        for (int nt = 0; nt < 8; nt++) {
            float p0 = exp2f((S[nt][0] - mn0) * LOG2E);
            float p1 = exp2f((S[nt][1] - mn0) * LOG2E);
            float p2 = exp2f((S[nt][2] - mn1) * LOG2E);
            float p3 = exp2f((S[nt][3] - mn1) * LOG2E);
            S[nt][0] = p0; S[nt][1] = p1; S[nt][2] = p2; S[nt][3] = p3;
            sum0 += p0 + p1; sum1 += p2 + p3;
        }
        sum0 += __shfl_xor_sync(0xffffffff, sum0, 1);
        sum0 += __shfl_xor_sync(0xffffffff, sum0, 2);
        sum1 += __shfl_xor_sync(0xffffffff, sum1, 1);
        sum1 += __shfl_xor_sync(0xffffffff, sum1, 2);
        l0 = l0 * a0 + sum0;
        l1 = l1 * a1 + sum1;
#pragma unroll
        for (int nt = 0; nt < 8; nt++) {
            O[nt][0] *= a0; O[nt][1] *= a0;
            O[nt][2] *= a1; O[nt][3] *= a1;
        }

        // O += P V
#pragma unroll
        for (int s = 0; s < 4; s++) {
            const int j0 = 2 * s, j1 = 2 * s + 1;
            unsigned ph[4], pl[4];
            ph[0] = pack2(S[j0][0], S[j0][1]);
            ph[1] = pack2(S[j0][2], S[j0][3]);
            ph[2] = pack2(S[j1][0], S[j1][1]);
            ph[3] = pack2(S[j1][2], S[j1][3]);
            pl[0] = pack2(resid(S[j0][0]), resid(S[j0][1]));
            pl[1] = pack2(resid(S[j0][2]), resid(S[j0][3]));
            pl[2] = pack2(resid(S[j1][0]), resid(S[j1][1]));
            pl[3] = pack2(resid(S[j1][2]), resid(S[j1][3]));
#pragma unroll
            for (int dt = 0; dt < 4; dt++) {
                int vrow = s * 16 + (lane & 15);
                int nb   = dt * 16 + ((lane >> 4) << 3);
                unsigned vh4[4], vl4[4];
                ldmx4t(vh4, Vh + vrow * ASTR + (nb >> 1));
                ldmx4t(vl4, Vl + vrow * ASTR + (nb >> 1));
                unsigned bh0[2] = { vh4[0], vh4[1] }, bl0[2] = { vl4[0], vl4[1] };
                unsigned bh1[2] = { vh4[2], vh4[3] }, bl1[2] = { vl4[2], vl4[3] };
                mma16816(O[2 * dt], ph, bh0);
                mma16816(O[2 * dt], ph, bl0);
                mma16816(O[2 * dt], pl, bh0);
                mma16816(O[2 * dt + 1], ph, bh1);
                mma16816(O[2 * dt + 1], ph, bl1);
                mma16816(O[2 * dt + 1], pl, bh1);
            }
        }
    }

    // epilogue
    float i0 = 1.f / l0, i1 = 1.f / l1;
    float* og = out + (long)(b * T_ + q0 + warp * 16 + rw) * D_ + h * HD_ + cw * 2;
#pragma unroll
    for (int nt = 0; nt < 8; nt++) {
        *(float2*)(og + nt * 8)           = make_float2(O[nt][0] * i0, O[nt][1] * i0);
        *(float2*)(og + 8 * D_ + nt * 8)  = make_float2(O[nt][2] * i1, O[nt][3] * i1);
    }
}

// ---------------------------------------------------------------------------
// Launch
// ---------------------------------------------------------------------------
extern "C" void kernel_launch(void* const* d_in, const int* in_sizes, int n_in,
                              void* d_out, int out_size)
{
    const float* x     = (const float*)d_in[0];
    const float* sinb  = (const float*)d_in[1];
    const float* cosb  = (const float*)d_in[2];
    const float* w_qkv = (const float*)d_in[3];
    const float* w_out = (const float*)d_in[4];
    float* out = (float*)d_out;

    float *qkv_ptr, *attn_ptr;
    __nv_bfloat16 *wqh, *wql, *woh, *wol;
    cudaGetSymbolAddress((void**)&qkv_ptr, g_qkv);
    cudaGetSymbolAddress((void**)&attn_ptr, g_attn);
    cudaGetSymbolAddress((void**)&wqh, g_wqkv_h);
    cudaGetSymbolAddress((void**)&wql, g_wqkv_l);
    cudaGetSymbolAddress((void**)&woh, g_wout_h);
    cudaGetSymbolAddress((void**)&wol, g_wout_l);

    const int gemm_smem = 2 * STAGE_U32 * 4;              // 81920 B
    const int attn_smem = 6 * 64 * ASTR * 4;              // 55296 B
    cudaFuncSetAttribute(gemm_bf16x3, cudaFuncAttributeMaxDynamicSharedMemorySize, gemm_smem);
    cudaFuncSetAttribute(attn_mma, cudaFuncAttributeMaxDynamicSharedMemorySize, attn_smem);

    // 0) split+transpose weights to bf16 hi/lo [N][K]
    wsplit_kernel<<<dim3(E_ / 32, D_ / 32), dim3(32, 8)>>>(w_qkv, wqh, wql, D_, E_);
    wsplit_kernel<<<dim3(D_ / 32, D_ / 32), dim3(32, 8)>>>(w_out, woh, wol, D_, D_);

    // 1) QKV projection
    gemm_bf16x3<<<dim3(E_ / 128, BT_ / 128), 256, gemm_smem>>>(x, wqh, wql, qkv_ptr, BT_, E_, D_);

    // 2) RoPE
    rope_kernel<<<BT_, 256>>>(sinb, cosb);

    // 3) Flash attention
    attn_mma<<<dim3(T_ / 64, NH_, B_), 128, attn_smem>>>(attn_ptr);

    // 4) Output projection
    gemm_bf16x3<<<dim3(D_ / 128, BT_ / 128), 256, gemm_smem>>>(attn_ptr, woh, wol, out, BT_, D_, D_);
}

// round 4
// speedup vs baseline: 2.8031x; 1.2414x over previous
#include <cuda_runtime.h>
#include <cuda_bf16.h>
#include <math.h>

// Problem constants
#define B_  2
#define T_  2048
#define D_  2048
#define E_  3072          // D + 2*KV_DIM
#define KV_ 512
#define HD_ 64
#define NH_ 32
#define BT_ 4096          // B*T

#define LOG2E 1.4426950408889634f

// Scratch (static __device__ arrays; allocation-free rule)
__device__ float g_qkv[BT_ * E_];                       // fp32 qkv (pre-rope)
__device__ __nv_bfloat16 g_xh[BT_ * D_],  g_xl[BT_ * D_];    // x split
__device__ __nv_bfloat16 g_qkvh[BT_ * E_], g_qkvl[BT_ * E_]; // roped qkv split
__device__ __nv_bfloat16 g_ath[BT_ * D_], g_atl[BT_ * D_];   // attn out split
__device__ __nv_bfloat16 g_wqkv_h[E_ * D_], g_wqkv_l[E_ * D_];
__device__ __nv_bfloat16 g_wout_h[D_ * D_], g_wout_l[D_ * D_];

// ---------------------------------------------------------------------------
// helpers
// ---------------------------------------------------------------------------
__device__ __forceinline__ unsigned pack2(float x, float y) {
    __nv_bfloat162 h = __floats2bfloat162_rn(x, y);   // .x in low half
    return *(unsigned*)&h;
}
__device__ __forceinline__ float resid(float x) {
    return x - __bfloat162float(__float2bfloat16_rn(x));
}
__device__ __forceinline__ void mma16816(float c[4], const unsigned a[4], const unsigned b[2]) {
    asm volatile(
        "mma.sync.aligned.m16n8k16.row.col.f32.bf16.bf16.f32 "
        "{%0,%1,%2,%3},{%4,%5,%6,%7},{%8,%9},{%0,%1,%2,%3};\n"
        : "+f"(c[0]), "+f"(c[1]), "+f"(c[2]), "+f"(c[3])
        : "r"(a[0]), "r"(a[1]), "r"(a[2]), "r"(a[3]), "r"(b[0]), "r"(b[1]));
}
__device__ __forceinline__ void cp16(void* dst_smem, const void* src) {
    unsigned d = (unsigned)__cvta_generic_to_shared(dst_smem);
    asm volatile("cp.async.cg.shared.global [%0], [%1], 16;\n" :: "r"(d), "l"(src));
}
__device__ __forceinline__ void cp_commit() { asm volatile("cp.async.commit_group;\n" ::: "memory"); }
__device__ __forceinline__ void cp_wait0()  { asm volatile("cp.async.wait_group 0;\n" ::: "memory"); }
__device__ __forceinline__ void cp_wait1()  { asm volatile("cp.async.wait_group 1;\n" ::: "memory"); }
__device__ __forceinline__ void ldmx4t(unsigned r[4], const void* p) {
    unsigned a = (unsigned)__cvta_generic_to_shared(p);
    asm volatile("ldmatrix.sync.aligned.m8n8.x4.trans.shared.b16 {%0,%1,%2,%3},[%4];\n"
                 : "=r"(r[0]), "=r"(r[1]), "=r"(r[2]), "=r"(r[3]) : "r"(a));
}

// ---------------------------------------------------------------------------
// x split: fp32 -> bf16 hi/lo
// ---------------------------------------------------------------------------
__global__ void xsplit_kernel(const float* __restrict__ X,
                              __nv_bfloat16* __restrict__ Xh,
                              __nv_bfloat16* __restrict__ Xl)
{
    long i = (long)(blockIdx.x * blockDim.x + threadIdx.x) * 4;
    if (i >= (long)BT_ * D_) return;
    float4 v = *(const float4*)(X + i);
    unsigned h0 = pack2(v.x, v.y), h1 = pack2(v.z, v.w);
    unsigned l0 = pack2(resid(v.x), resid(v.y)), l1 = pack2(resid(v.z), resid(v.w));
    *(uint2*)(Xh + i) = make_uint2(h0, h1);
    *(uint2*)(Xl + i) = make_uint2(l0, l1);
}

// ---------------------------------------------------------------------------
// Weight split+transpose: W[K][N] fp32 -> Wt_hi/Wt_lo [N][K] bf16
// ---------------------------------------------------------------------------
__global__ void wsplit_kernel(const float* __restrict__ W,
                              __nv_bfloat16* __restrict__ Oh,
                              __nv_bfloat16* __restrict__ Ol, int K, int N)
{
    __shared__ float t[32][33];
    int n0 = blockIdx.x * 32, k0 = blockIdx.y * 32;
    for (int i = threadIdx.y; i < 32; i += 8)
        t[i][threadIdx.x] = W[(long)(k0 + i) * N + n0 + threadIdx.x];
    __syncthreads();
    for (int i = threadIdx.y; i < 32; i += 8) {
        float v = t[threadIdx.x][i];
        long o = (long)(n0 + i) * K + k0 + threadIdx.x;
        __nv_bfloat16 h = __float2bfloat16_rn(v);
        Oh[o] = h;
        Ol[o] = __float2bfloat16_rn(v - __bfloat162float(h));
    }
}

// ---------------------------------------------------------------------------
// GEMM (bf16x3 tensor-core): C[M,N] = A[M,K] * W[K,N]
// A pre-split [M][K] bf16 hi/lo; W pre-split/transposed [N][K] bf16 hi/lo.
// 128x128x32 tiles, 256 threads, warptile 32x64, 3-stage cp.async ring.
// ---------------------------------------------------------------------------
#define GSTR 20                       // u32 words per smem row (40 halves)
#define STAGE_U32 (4 * 128 * GSTR)    // Ah,Al,Bh,Bl per stage (40960 B)

__global__ void __launch_bounds__(256) gemm_bf16x3(
    const __nv_bfloat16* __restrict__ Ah_g, const __nv_bfloat16* __restrict__ Al_g,
    const __nv_bfloat16* __restrict__ Bh_g, const __nv_bfloat16* __restrict__ Bl_g,
    float* __restrict__ C, int M, int N, int K)
{
    extern __shared__ __align__(16) unsigned smem[];
    const int tid = threadIdx.x, lane = tid & 31, warp = tid >> 5;
    const int row0 = blockIdx.y * 128, col0 = blockIdx.x * 128;
    const int m0 = (warp >> 1) * 32, n0w = (warp & 1) * 64;
    const int rw = lane >> 2, cw = lane & 3;
    const int nk = K >> 5;

    float acc[2][8][4];
#pragma unroll
    for (int mt = 0; mt < 2; mt++)
#pragma unroll
        for (int nt = 0; nt < 8; nt++)
#pragma unroll
            for (int e = 0; e < 4; e++) acc[mt][nt][e] = 0.f;

    auto issue = [&](int st, int kb) {
        unsigned* base = smem + st * STAGE_U32;
#pragma unroll
        for (int l = 0; l < 8; l++) {
            int idx = tid + l * 256;                 // 0..2047
            int hf  = idx >> 10;                     // 0=A, 1=B
            int mat = (idx >> 9) & 1;                // 0=hi, 1=lo
            int r   = (idx >> 2) & 127;
            int c8  = (idx & 3) << 3;
            const __nv_bfloat16* src;
            long grow;
            if (hf) { src = mat ? Bl_g : Bh_g; grow = col0 + r; }
            else    { src = mat ? Al_g : Ah_g; grow = row0 + r; }
            unsigned* dst = base + (hf * 2 + mat) * 128 * GSTR + r * GSTR + (c8 >> 1);
            cp16(dst, src + grow * K + kb * 32 + c8);
        }
        cp_commit();
    };

    issue(0, 0);
    if (nk > 1) issue(1, 1);

    for (int kb = 0; kb < nk; kb++) {
        const int st = kb % 3;
        if (kb + 1 < nk) cp_wait1(); else cp_wait0();
        __syncthreads();

        unsigned* base = smem + st * STAGE_U32;
        unsigned* Ah = base;
        unsigned* Al = base + 128 * GSTR;
        unsigned* Bh = base + 2 * 128 * GSTR;
        unsigned* Bl = base + 3 * 128 * GSTR;

#pragma unroll
        for (int s = 0; s < 2; s++) {
            unsigned ah[2][4], al[2][4];
#pragma unroll
            for (int mt = 0; mt < 2; mt++) {
                int fb = (m0 + mt * 16 + rw) * GSTR + s * 8 + cw;
                ah[mt][0] = Ah[fb];
                ah[mt][1] = Ah[fb + 8 * GSTR];
                ah[mt][2] = Ah[fb + 4];
                ah[mt][3] = Ah[fb + 8 * GSTR + 4];
                al[mt][0] = Al[fb];
                al[mt][1] = Al[fb + 8 * GSTR];
                al[mt][2] = Al[fb + 4];
                al[mt][3] = Al[fb + 8 * GSTR + 4];
            }
#pragma unroll
            for (int nt = 0; nt < 8; nt++) {
                int bb = (n0w + nt * 8 + rw) * GSTR + s * 8 + cw;
                unsigned bh[2] = { Bh[bb], Bh[bb + 4] };
                unsigned bl[2] = { Bl[bb], Bl[bb + 4] };
#pragma unroll
                for (int mt = 0; mt < 2; mt++) {
                    mma16816(acc[mt][nt], ah[mt], bh);
                    mma16816(acc[mt][nt], ah[mt], bl);
                    mma16816(acc[mt][nt], al[mt], bh);
                }
            }
        }

        if (kb + 2 < nk) issue((kb + 2) % 3, kb + 2);
    }

#pragma unroll
    for (int mt = 0; mt < 2; mt++) {
#pragma unroll
        for (int nt = 0; nt < 8; nt++) {
            int row = row0 + m0 + mt * 16 + rw;
            int col = col0 + n0w + nt * 8 + cw * 2;
            *(float2*)(C + (long)row * N + col)       = make_float2(acc[mt][nt][0], acc[mt][nt][1]);
            *(float2*)(C + (long)(row + 8) * N + col) = make_float2(acc[mt][nt][2], acc[mt][nt][3]);
        }
    }
}

// ---------------------------------------------------------------------------
// RoPE + split: read fp32 qkv, rotate q/k, write bf16 hi/lo qkv (v passthrough)
// ---------------------------------------------------------------------------
__global__ void rope_split_kernel(const float* __restrict__ sinb, const float* __restrict__ cosb)
{
    const int bt = blockIdx.x;
    const int t  = bt & (T_ - 1);
    const float* src = g_qkv + (long)bt * E_;
    __nv_bfloat16* dh = g_qkvh + (long)bt * E_;
    __nv_bfloat16* dl = g_qkvl + (long)bt * E_;

    for (int p = threadIdx.x; p < 1280; p += blockDim.x) {
        int hh = p >> 5, i = p & 31;
        int off = (hh < 32) ? hh * HD_ : D_ + (hh - 32) * HD_;
        float u1 = src[off + i];
        float u2 = src[off + i + 32];
        float c1 = cosb[t * HD_ + i],      s1 = sinb[t * HD_ + i];
        float c2 = cosb[t * HD_ + i + 32], s2 = sinb[t * HD_ + i + 32];
        float o1 = u1 * c1 - u2 * s1;
        float o2 = u2 * c2 + u1 * s2;
        __nv_bfloat16 h1 = __float2bfloat16_rn(o1);
        dh[off + i]      = h1;
        dl[off + i]      = __float2bfloat16_rn(o1 - __bfloat162float(h1));
        __nv_bfloat16 h2 = __float2bfloat16_rn(o2);
        dh[off + i + 32] = h2;
        dl[off + i + 32] = __float2bfloat16_rn(o2 - __bfloat162float(h2));
    }
    for (int i = threadIdx.x; i < KV_; i += blockDim.x) {
        float v = src[D_ + KV_ + i];
        __nv_bfloat16 h = __float2bfloat16_rn(v);
        dh[D_ + KV_ + i] = h;
        dl[D_ + KV_ + i] = __float2bfloat16_rn(v - __bfloat162float(h));
    }
}

// ---------------------------------------------------------------------------
// Flash attention (causal, GQA) on tensor cores. 256 threads (8 warps), q-tile
// 128 rows (16 per warp). K/V tiles 64 rows, double-buffered cp.async. All
// operands pre-split bf16. Output written pre-split bf16 hi/lo.
// ---------------------------------------------------------------------------
#define ASTR 36
#define QWORDS (128 * ASTR)
#define TWORDS (64 * ASTR)
#define ATTN_STAGE_WORDS (4 * TWORDS)
#define ATTN_SMEM_BYTES ((2 * QWORDS + 2 * ATTN_STAGE_WORDS) * 4)

__global__ void __launch_bounds__(256) attn_mma(
    const __nv_bfloat16* __restrict__ qkvh, const __nv_bfloat16* __restrict__ qkvl,
    __nv_bfloat16* __restrict__ oh, __nv_bfloat16* __restrict__ ol)
{
    extern __shared__ __align__(16) unsigned asmem[];
    unsigned* Qh = asmem;
    unsigned* Ql = Qh + QWORDS;

    const int tid = threadIdx.x, lane = tid & 31, warp = tid >> 5;
    const int qb = blockIdx.x, h = blockIdx.y, b = blockIdx.z;
    const int q0 = qb * 128;
    const int rw = lane >> 2, cw = lane & 3;
    const int qrow = warp * 16 + rw;
    const int wrow0 = q0 + warp * 16;

    const long qbase = (long)(b * T_) * E_ + h * HD_;
    const long kbase = (long)(b * T_) * E_ + D_ + (h >> 2) * HD_;
    const long vbase = kbase + KV_;

    // issue Q (one cp.async group)
#pragma unroll
    for (int l = 0; l < 8; l++) {
        int idx = tid + l * 256;
        int mat = idx >> 10, r = (idx >> 3) & 127, cc = idx & 7;
        const __nv_bfloat16* src = (mat ? qkvl : qkvh) + qbase + (long)(q0 + r) * E_ + cc * 8;
        cp16((mat ? Ql : Qh) + r * ASTR + cc * 4, src);
    }
    cp_commit();

    const int njb = 2 * qb + 2;

    auto issueKV = [&](int jb, int st) {
        unsigned* sb = asmem + 2 * QWORDS + st * ATTN_STAGE_WORDS;
        const int k0 = jb * 64;
#pragma unroll
        for (int l = 0; l < 8; l++) {
            int idx = tid + l * 256;
            int mat = idx >> 9;                 // 0:Kh 1:Kl 2:Vh 3:Vl
            int r = (idx >> 3) & 63, cc = idx & 7;
            const __nv_bfloat16* gsrc = (mat & 1) ? qkvl : qkvh;
            long base = (mat >= 2) ? vbase : kbase;
            cp16(sb + mat * TWORDS + r * ASTR + cc * 4,
                 gsrc + base + (long)(k0 + r) * E_ + cc * 8);
        }
        cp_commit();
    };

    issueKV(0, 0);
    issueKV(1, 1);

    float O[8][4];
#pragma unroll
    for (int nt = 0; nt < 8; nt++)
#pragma unroll
        for (int e = 0; e < 4; e++) O[nt][e] = 0.f;
    float m0v = -INFINITY, m1v = -INFINITY, l0v = 0.f, l1v = 0.f;

    for (int jb = 0; jb < njb; jb++) {
        const int st = jb & 1;
        const int k0 = jb * 64;
        if (jb + 1 < njb) cp_wait1(); else cp_wait0();
        __syncthreads();

        const bool active = (k0 <= wrow0 + 15);
        if (active) {
            unsigned* sb = asmem + 2 * QWORDS + st * ATTN_STAGE_WORDS;
            unsigned* Kh = sb;
            unsigned* Kl = sb + TWORDS;
            unsigned* Vh = sb + 2 * TWORDS;
            unsigned* Vl = sb + 3 * TWORDS;

            // S = Q K^T
            float S[8][4];
#pragma unroll
            for (int nt = 0; nt < 8; nt++)
#pragma unroll
                for (int e = 0; e < 4; e++) S[nt][e] = 0.f;

#pragma unroll
            for (int s = 0; s < 4; s++) {
                unsigned qh[4], ql[4];
                int qb_ = qrow * ASTR + s * 8 + cw;
                qh[0] = Qh[qb_];        qh[1] = Qh[qb_ + 8 * ASTR];
                qh[2] = Qh[qb_ + 4];    qh[3] = Qh[qb_ + 8 * ASTR + 4];
                ql[0] = Ql[qb_];        ql[1] = Ql[qb_ + 8 * ASTR];
                ql[2] = Ql[qb_ + 4];    ql[3] = Ql[qb_ + 8 * ASTR + 4];
#pragma unroll
                for (int nt = 0; nt < 8; nt++) {
                    int kb_ = (nt * 8 + rw) * ASTR + s * 8 + cw;
                    unsigned kh[2] = { Kh[kb_], Kh[kb_ + 4] };
                    unsigned kl[2] = { Kl[kb_], Kl[kb_ + 4] };
                    mma16816(S[nt], qh, kh);
                    mma16816(S[nt], qh, kl);
                    mma16816(S[nt], ql, kh);
                }
            }

            const float sc = 0.125f;
            if (k0 + 63 > wrow0) {      // diagonal tile for this warp
#pragma unroll
                for (int nt = 0; nt < 8; nt++)
#pragma unroll
                    for (int e = 0; e < 4; e++) {
                        int r = q0 + warp * 16 + rw + ((e >= 2) ? 8 : 0);
                        int c = k0 + nt * 8 + cw * 2 + (e & 1);
                        S[nt][e] = (c <= r) ? S[nt][e] * sc : -1e30f;
                    }
            } else {
#pragma unroll
                for (int nt = 0; nt < 8; nt++)
#pragma unroll
                    for (int e = 0; e < 4; e++) S[nt][e] *= sc;
            }

            // online softmax
            float mx0 = -INFINITY, mx1 = -INFINITY;
#pragma unroll
            for (int nt = 0; nt < 8; nt++) {
                mx0 = fmaxf(mx0, fmaxf(S[nt][0], S[nt][1]));
                mx1 = fmaxf(mx1, fmaxf(S[nt][2], S[nt][3]));
            }
            mx0 = fmaxf(mx0, __shfl_xor_sync(0xffffffff, mx0, 1));
            mx0 = fmaxf(mx0, __shfl_xor_sync(0xffffffff, mx0, 2));
            mx1 = fmaxf(mx1, __shfl_xor_sync(0xffffffff, mx1, 1));
            mx1 = fmaxf(mx1, __shfl_xor_sync(0xffffffff, mx1, 2));
            float mn0 = fmaxf(m0v, mx0), mn1 = fmaxf(m1v, mx1);
            float a0 = exp2f((m0v - mn0) * LOG2E), a1 = exp2f((m1v - mn1) * LOG2E);
            m0v = mn0; m1v = mn1;
            float sum0 = 0.f, sum1 = 0.f;
#pragma unroll
            for (int nt = 0; nt < 8; nt++) {
                float p0 = exp2f((S[nt][0] - mn0) * LOG2E);
                float p1 = exp2f((S[nt][1] - mn0) * LOG2E);
                float p2 = exp2f((S[nt][2] - mn1) * LOG2E);
                float p3 = exp2f((S[nt][3] - mn1) * LOG2E);
                S[nt][0] = p0; S[nt][1] = p1; S[nt][2] = p2; S[nt][3] = p3;
                sum0 += p0 + p1; sum1 += p2 + p3;
            }
            sum0 += __shfl_xor_sync(0xffffffff, sum0, 1);
            sum0 += __shfl_xor_sync(0xffffffff, sum0, 2);
            sum1 += __shfl_xor_sync(0xffffffff, sum1, 1);
            sum1 += __shfl_xor_sync(0xffffffff, sum1, 2);
            l0v = l0v * a0 + sum0;
            l1v = l1v * a1 + sum1;
#pragma unroll
            for (int nt = 0; nt < 8; nt++) {
                O[nt][0] *= a0; O[nt][1] *= a0;
                O[nt][2] *= a1; O[nt][3] *= a1;
            }

            // O += P V
#pragma unroll
            for (int s = 0; s < 4; s++) {
                const int j0 = 2 * s, j1 = 2 * s + 1;
                unsigned ph[4], pl[4];
                ph[0] = pack2(S[j0][0], S[j0][1]);
                ph[1] = pack2(S[j0][2], S[j0][3]);
                ph[2] = pack2(S[j1][0], S[j1][1]);
                ph[3] = pack2(S[j1][2], S[j1][3]);
                pl[0] = pack2(resid(S[j0][0]), resid(S[j0][1]));
                pl[1] = pack2(resid(S[j0][2]), resid(S[j0][3]));
                pl[2] = pack2(resid(S[j1][0]), resid(S[j1][1]));
                pl[3] = pack2(resid(S[j1][2]), resid(S[j1][3]));
#pragma unroll
                for (int dt = 0; dt < 4; dt++) {
                    int vrow = s * 16 + (lane & 15);
                    int nb   = dt * 16 + ((lane >> 4) << 3);
                    unsigned vh4[4], vl4[4];
                    ldmx4t(vh4, Vh + vrow * ASTR + (nb >> 1));
                    ldmx4t(vl4, Vl + vrow * ASTR + (nb >> 1));
                    unsigned bh0[2] = { vh4[0], vh4[1] }, bl0[2] = { vl4[0], vl4[1] };
                    unsigned bh1[2] = { vh4[2], vh4[3] }, bl1[2] = { vl4[2], vl4[3] };
                    mma16816(O[2 * dt], ph, bh0);
                    mma16816(O[2 * dt], ph, bl0);
                    mma16816(O[2 * dt], pl, bh0);
                    mma16816(O[2 * dt + 1], ph, bh1);
                    mma16816(O[2 * dt + 1], ph, bl1);
                    mma16816(O[2 * dt + 1], pl, bh1);
                }
            }
        }
        __syncthreads();
        if (jb + 2 < njb) issueKV(jb + 2, st);
    }

    // epilogue: normalize and write split bf16
    float i0 = 1.f / l0v, i1 = 1.f / l1v;
    long row = (long)(b * T_ + q0 + warp * 16 + rw);
    long colb = h * HD_ + cw * 2;
#pragma unroll
    for (int nt = 0; nt < 8; nt++) {
        float o0 = O[nt][0] * i0, o1 = O[nt][1] * i0;
        float o2 = O[nt][2] * i1, o3 = O[nt][3] * i1;
        long p0 = row * D_ + colb + nt * 8;
        long p1 = (row + 8) * D_ + colb + nt * 8;
        *(unsigned*)(oh + p0) = pack2(o0, o1);
        *(unsigned*)(ol + p0) = pack2(resid(o0), resid(o1));
        *(unsigned*)(oh + p1) = pack2(o2, o3);
        *(unsigned*)(ol + p1) = pack2(resid(o2), resid(o3));
    }
}

// ---------------------------------------------------------------------------
// Launch
// ---------------------------------------------------------------------------
extern "C" void kernel_launch(void* const* d_in, const int* in_sizes, int n_in,
                              void* d_out, int out_size)
{
    const float* x     = (const float*)d_in[0];
    const float* sinb  = (const float*)d_in[1];
    const float* cosb  = (const float*)d_in[2];
    const float* w_qkv = (const float*)d_in[3];
    const float* w_out = (const float*)d_in[4];
    float* out = (float*)d_out;

    float* qkv_ptr;
    __nv_bfloat16 *xh, *xl, *qh, *ql, *ath, *atl, *wqh, *wql, *woh, *wol;
    cudaGetSymbolAddress((void**)&qkv_ptr, g_qkv);
    cudaGetSymbolAddress((void**)&xh, g_xh);
    cudaGetSymbolAddress((void**)&xl, g_xl);
    cudaGetSymbolAddress((void**)&qh, g_qkvh);
    cudaGetSymbolAddress((void**)&ql, g_qkvl);
    cudaGetSymbolAddress((void**)&ath, g_ath);
    cudaGetSymbolAddress((void**)&atl, g_atl);
    cudaGetSymbolAddress((void**)&wqh, g_wqkv_h);
    cudaGetSymbolAddress((void**)&wql, g_wqkv_l);
    cudaGetSymbolAddress((void**)&woh, g_wout_h);
    cudaGetSymbolAddress((void**)&wol, g_wout_l);

    const int gemm_smem = 3 * STAGE_U32 * 4;   // 122880 B
    const int attn_smem = ATTN_SMEM_BYTES;     // 110592 B
    cudaFuncSetAttribute(gemm_bf16x3, cudaFuncAttributeMaxDynamicSharedMemorySize, gemm_smem);
    cudaFuncSetAttribute(attn_mma, cudaFuncAttributeMaxDynamicSharedMemorySize, attn_smem);

    // 0) splits
    xsplit_kernel<<<(BT_ * D_ / 4 + 255) / 256, 256>>>(x, xh, xl);
    wsplit_kernel<<<dim3(E_ / 32, D_ / 32), dim3(32, 8)>>>(w_qkv, wqh, wql, D_, E_);
    wsplit_kernel<<<dim3(D_ / 32, D_ / 32), dim3(32, 8)>>>(w_out, woh, wol, D_, D_);

    // 1) QKV projection
    gemm_bf16x3<<<dim3(E_ / 128, BT_ / 128), 256, gemm_smem>>>(xh, xl, wqh, wql, qkv_ptr, BT_, E_, D_);

    // 2) RoPE + split
    rope_split_kernel<<<BT_, 256>>>(sinb, cosb);

    // 3) Flash attention (q-tile 128)
    attn_mma<<<dim3(T_ / 128, NH_, B_), 256, attn_smem>>>(qh, ql, ath, atl);

    // 4) Output projection
    gemm_bf16x3<<<dim3(D_ / 128, BT_ / 128), 256, gemm_smem>>>(ath, atl, woh, wol, out, BT_, D_, D_);
}

// round 7
// speedup vs baseline: 3.2098x; 1.1451x over previous
#include <cuda_runtime.h>
#include <cuda_bf16.h>
#include <math.h>

// Problem constants
#define B_  2
#define T_  2048
#define D_  2048
#define E_  3072          // D + 2*KV_DIM
#define KV_ 512
#define HD_ 64
#define NH_ 32
#define BT_ 4096          // B*T

#define LOG2E 1.4426950408889634f

// Scratch (static __device__ arrays; allocation-free rule)
__device__ __nv_bfloat16 g_xh[BT_ * D_],  g_xl[BT_ * D_];    // x split
__device__ __nv_bfloat16 g_qkvh[BT_ * E_], g_qkvl[BT_ * E_]; // roped qkv split
__device__ __nv_bfloat16 g_ath[BT_ * D_], g_atl[BT_ * D_];   // attn out split
__device__ __nv_bfloat16 g_wqkv_h[E_ * D_], g_wqkv_l[E_ * D_];
__device__ __nv_bfloat16 g_wout_h[D_ * D_], g_wout_l[D_ * D_];

// ---------------------------------------------------------------------------
// helpers
// ---------------------------------------------------------------------------
__device__ __forceinline__ unsigned pack2(float x, float y) {
    __nv_bfloat162 h = __floats2bfloat162_rn(x, y);   // .x in low half
    return *(unsigned*)&h;
}
__device__ __forceinline__ float resid(float x) {
    return x - __bfloat162float(__float2bfloat16_rn(x));
}
__device__ __forceinline__ void mma16816(float c[4], const unsigned a[4], const unsigned b[2]) {
    asm volatile(
        "mma.sync.aligned.m16n8k16.row.col.f32.bf16.bf16.f32 "
        "{%0,%1,%2,%3},{%4,%5,%6,%7},{%8,%9},{%0,%1,%2,%3};\n"
        : "+f"(c[0]), "+f"(c[1]), "+f"(c[2]), "+f"(c[3])
        : "r"(a[0]), "r"(a[1]), "r"(a[2]), "r"(a[3]), "r"(b[0]), "r"(b[1]));
}
__device__ __forceinline__ void cp16(void* dst_smem, const void* src) {
    unsigned d = (unsigned)__cvta_generic_to_shared(dst_smem);
    asm volatile("cp.async.cg.shared.global [%0], [%1], 16;\n" :: "r"(d), "l"(src));
}
__device__ __forceinline__ void cp_commit() { asm volatile("cp.async.commit_group;\n" ::: "memory"); }
__device__ __forceinline__ void cp_wait0()  { asm volatile("cp.async.wait_group 0;\n" ::: "memory"); }
__device__ __forceinline__ void cp_wait1()  { asm volatile("cp.async.wait_group 1;\n" ::: "memory"); }
__device__ __forceinline__ void ldmx4(unsigned r[4], const void* p) {
    unsigned a = (unsigned)__cvta_generic_to_shared(p);
    asm volatile("ldmatrix.sync.aligned.m8n8.x4.shared.b16 {%0,%1,%2,%3},[%4];\n"
                 : "=r"(r[0]), "=r"(r[1]), "=r"(r[2]), "=r"(r[3]) : "r"(a));
}
__device__ __forceinline__ void ldmx4t(unsigned r[4], const void* p) {
    unsigned a = (unsigned)__cvta_generic_to_shared(p);
    asm volatile("ldmatrix.sync.aligned.m8n8.x4.trans.shared.b16 {%0,%1,%2,%3},[%4];\n"
                 : "=r"(r[0]), "=r"(r[1]), "=r"(r[2]), "=r"(r[3]) : "r"(a));
}

// ---------------------------------------------------------------------------
// x split: fp32 -> bf16 hi/lo
// ---------------------------------------------------------------------------
__global__ void xsplit_kernel(const float* __restrict__ X,
                              __nv_bfloat16* __restrict__ Xh,
                              __nv_bfloat16* __restrict__ Xl)
{
    long i = (long)(blockIdx.x * blockDim.x + threadIdx.x) * 4;
    if (i >= (long)BT_ * D_) return;
    float4 v = *(const float4*)(X + i);
    unsigned h0 = pack2(v.x, v.y), h1 = pack2(v.z, v.w);
    unsigned l0 = pack2(resid(v.x), resid(v.y)), l1 = pack2(resid(v.z), resid(v.w));
    *(uint2*)(Xh + i) = make_uint2(h0, h1);
    *(uint2*)(Xl + i) = make_uint2(l0, l1);
}

// ---------------------------------------------------------------------------
// Weight split+transpose: W[K][N] fp32 -> Wt_hi/Wt_lo [N][K] bf16
// ---------------------------------------------------------------------------
__global__ void wsplit_kernel(const float* __restrict__ W,
                              __nv_bfloat16* __restrict__ Oh,
                              __nv_bfloat16* __restrict__ Ol, int K, int N)
{
    __shared__ float t[32][33];
    int n0 = blockIdx.x * 32, k0 = blockIdx.y * 32;
    for (int i = threadIdx.y; i < 32; i += 8)
        t[i][threadIdx.x] = W[(long)(k0 + i) * N + n0 + threadIdx.x];
    __syncthreads();
    for (int i = threadIdx.y; i < 32; i += 8) {
        float v = t[threadIdx.x][i];
        long o = (long)(n0 + i) * K + k0 + threadIdx.x;
        __nv_bfloat16 h = __float2bfloat16_rn(v);
        Oh[o] = h;
        Ol[o] = __float2bfloat16_rn(v - __bfloat162float(h));
    }
}

// ---------------------------------------------------------------------------
// GEMM (bf16x3 tensor-core): C[M,N] = A[M,K] * W[K,N]
// A pre-split [M][K] bf16 hi/lo; W pre-split/transposed [N][K] bf16 hi/lo.
// 128x128x32 tiles, 256 threads, warptile 32x64, 2-stage ring (2 CTAs/SM),
// ldmatrix.x4 fragment loads.
// mode 0: write C fp32.  mode 1: fused RoPE + bf16 hi/lo split -> Ch/Cl.
// ---------------------------------------------------------------------------
#define GSTR 20                       // u32 words per smem row (40 halves)
#define STAGE_U32 (4 * 128 * GSTR)    // Ah,Al,Bh,Bl per stage (40960 B)

__global__ void __launch_bounds__(256, 2) gemm_bf16x3(
    const __nv_bfloat16* __restrict__ Ah_g, const __nv_bfloat16* __restrict__ Al_g,
    const __nv_bfloat16* __restrict__ Bh_g, const __nv_bfloat16* __restrict__ Bl_g,
    float* __restrict__ C, int M, int N, int K, int mode,
    const float* __restrict__ sinb, const float* __restrict__ cosb,
    __nv_bfloat16* __restrict__ Ch, __nv_bfloat16* __restrict__ Cl)
{
    extern __shared__ __align__(16) unsigned smem[];
    const int tid = threadIdx.x, lane = tid & 31, warp = tid >> 5;
    const int row0 = blockIdx.y * 128, col0 = blockIdx.x * 128;
    const int m0 = (warp >> 1) * 32, n0w = (warp & 1) * 64;
    const int rw = lane >> 2, cw = lane & 3;
    const int nk = K >> 5;

    float acc[2][8][4];
#pragma unroll
    for (int mt = 0; mt < 2; mt++)
#pragma unroll
        for (int nt = 0; nt < 8; nt++)
#pragma unroll
            for (int e = 0; e < 4; e++) acc[mt][nt][e] = 0.f;

    auto issue = [&](int st, int kb) {
        unsigned* base = smem + st * STAGE_U32;
#pragma unroll
        for (int l = 0; l < 8; l++) {
            int idx = tid + l * 256;                 // 0..2047
            int hf  = idx >> 10;                     // 0=A, 1=B
            int mat = (idx >> 9) & 1;                // 0=hi, 1=lo
            int r   = (idx >> 2) & 127;
            int c8  = (idx & 3) << 3;
            const __nv_bfloat16* src;
            long grow;
            if (hf) { src = mat ? Bl_g : Bh_g; grow = col0 + r; }
            else    { src = mat ? Al_g : Ah_g; grow = row0 + r; }
            unsigned* dst = base + (hf * 2 + mat) * 128 * GSTR + r * GSTR + (c8 >> 1);
            cp16(dst, src + grow * K + kb * 32 + c8);
        }
        cp_commit();
    };

    issue(0, 0);
    issue(1, 1);

    for (int kb = 0; kb < nk; kb++) {
        const int st = kb & 1;
        if (kb + 1 < nk) cp_wait1(); else cp_wait0();
        __syncthreads();

        unsigned* base = smem + st * STAGE_U32;
        unsigned* Ah = base;
        unsigned* Al = base + 128 * GSTR;
        unsigned* Bh = base + 2 * 128 * GSTR;
        unsigned* Bl = base + 3 * 128 * GSTR;

#pragma unroll
        for (int s = 0; s < 2; s++) {
            unsigned ah[2][4], al[2][4];
#pragma unroll
            for (int mt = 0; mt < 2; mt++) {
                int row = m0 + mt * 16 + (lane & 15);
                int kw  = s * 8 + ((lane >> 4) << 2);
                ldmx4(ah[mt], Ah + row * GSTR + kw);
                ldmx4(al[mt], Al + row * GSTR + kw);
            }
#pragma unroll
            for (int ntp = 0; ntp < 4; ntp++) {
                int row = n0w + ntp * 16 + ((lane >> 4) << 3) + (lane & 7);
                int kw  = s * 8 + ((lane & 8) >> 1);
                unsigned bh4[4], bl4[4];
                ldmx4(bh4, Bh + row * GSTR + kw);
                ldmx4(bl4, Bl + row * GSTR + kw);
                unsigned bh0[2] = { bh4[0], bh4[1] }, bl0[2] = { bl4[0], bl4[1] };
                unsigned bh1[2] = { bh4[2], bh4[3] }, bl1[2] = { bl4[2], bl4[3] };
#pragma unroll
                for (int mt = 0; mt < 2; mt++) {
                    mma16816(acc[mt][2 * ntp],     ah[mt], bh0);
                    mma16816(acc[mt][2 * ntp],     ah[mt], bl0);
                    mma16816(acc[mt][2 * ntp],     al[mt], bh0);
                    mma16816(acc[mt][2 * ntp + 1], ah[mt], bh1);
                    mma16816(acc[mt][2 * ntp + 1], ah[mt], bl1);
                    mma16816(acc[mt][2 * ntp + 1], al[mt], bh1);
                }
            }
        }

        __syncthreads();
        if (kb + 2 < nk) issue(st, kb + 2);
    }

    // ---- epilogue
    if (mode == 0) {
#pragma unroll
        for (int mt = 0; mt < 2; mt++) {
#pragma unroll
            for (int nt = 0; nt < 8; nt++) {
                int row = row0 + m0 + mt * 16 + rw;
                int col = col0 + n0w + nt * 8 + cw * 2;
                *(float2*)(C + (long)row * N + col)       = make_float2(acc[mt][nt][0], acc[mt][nt][1]);
                *(float2*)(C + (long)(row + 8) * N + col) = make_float2(acc[mt][nt][2], acc[mt][nt][3]);
            }
        }
    } else {
        const bool isv = (col0 + n0w) >= (D_ + KV_);
#pragma unroll
        for (int mt = 0; mt < 2; mt++) {
            int rbase = row0 + m0 + mt * 16 + rw;
#pragma unroll
            for (int half = 0; half < 2; half++) {
                int r = rbase + half * 8;
                int t = r & (T_ - 1);
                if (!isv) {
#pragma unroll
                    for (int nt = 0; nt < 4; nt++) {
                        float ol0[2], ol1[2];
#pragma unroll
                        for (int d = 0; d < 2; d++) {
                            int e = half * 2 + d;
                            float u1 = acc[mt][nt][e];
                            float u2 = acc[mt][nt + 4][e];
                            int i = nt * 8 + cw * 2 + d;
                            float c1 = cosb[t * HD_ + i],      s1 = sinb[t * HD_ + i];
                            float c2 = cosb[t * HD_ + i + 32], s2 = sinb[t * HD_ + i + 32];
                            ol0[d] = u1 * c1 - u2 * s1;
                            ol1[d] = u2 * c2 + u1 * s2;
                        }
                        long p = (long)r * E_ + col0 + n0w + nt * 8 + cw * 2;
                        *(unsigned*)(Ch + p)      = pack2(ol0[0], ol0[1]);
                        *(unsigned*)(Cl + p)      = pack2(resid(ol0[0]), resid(ol0[1]));
                        *(unsigned*)(Ch + p + 32) = pack2(ol1[0], ol1[1]);
                        *(unsigned*)(Cl + p + 32) = pack2(resid(ol1[0]), resid(ol1[1]));
                    }
                } else {
#pragma unroll
                    for (int nt = 0; nt < 8; nt++) {
                        float v0 = acc[mt][nt][half * 2];
                        float v1 = acc[mt][nt][half * 2 + 1];
                        long p = (long)r * E_ + col0 + n0w + nt * 8 + cw * 2;
                        *(unsigned*)(Ch + p) = pack2(v0, v1);
                        *(unsigned*)(Cl + p) = pack2(resid(v0), resid(v1));
                    }
                }
            }
        }
    }
}

// ---------------------------------------------------------------------------
// Flash attention (causal, GQA) on tensor cores. 256 threads (8 warps), q-tile
// 128 rows (16 per warp). K/V tiles 64 rows, double-buffered cp.async.
// ldmatrix.x4 for Q/K fragments; ldmatrix.x4.trans for V.
// ---------------------------------------------------------------------------
#define ASTR 36
#define QWORDS (128 * ASTR)
#define TWORDS (64 * ASTR)
#define ATTN_STAGE_WORDS (4 * TWORDS)
#define ATTN_SMEM_BYTES ((2 * QWORDS + 2 * ATTN_STAGE_WORDS) * 4)

__global__ void __launch_bounds__(256) attn_mma(
    const __nv_bfloat16* __restrict__ qkvh, const __nv_bfloat16* __restrict__ qkvl,
    __nv_bfloat16* __restrict__ oh, __nv_bfloat16* __restrict__ ol)
{
    extern __shared__ __align__(16) unsigned asmem[];
    unsigned* Qh = asmem;
    unsigned* Ql = Qh + QWORDS;

    const int tid = threadIdx.x, lane = tid & 31, warp = tid >> 5;
    const int qb = blockIdx.x, h = blockIdx.y, b = blockIdx.z;
    const int q0 = qb * 128;
    const int rw = lane >> 2, cw = lane & 3;
    const int wrow0 = q0 + warp * 16;

    const long qbase = (long)(b * T_) * E_ + h * HD_;
    const long kbase = (long)(b * T_) * E_ + D_ + (h >> 2) * HD_;
    const long vbase = kbase + KV_;

    // issue Q (one cp.async group)
#pragma unroll
    for (int l = 0; l < 8; l++) {
        int idx = tid + l * 256;
        int mat = idx >> 10, r = (idx >> 3) & 127, cc = idx & 7;
        const __nv_bfloat16* src = (mat ? qkvl : qkvh) + qbase + (long)(q0 + r) * E_ + cc * 8;
        cp16((mat ? Ql : Qh) + r * ASTR + cc * 4, src);
    }
    cp_commit();

    const int njb = 2 * qb + 2;

    auto issueKV = [&](int jb, int st) {
        unsigned* sb = asmem + 2 * QWORDS + st * ATTN_STAGE_WORDS;
        const int k0 = jb * 64;
#pragma unroll
        for (int l = 0; l < 8; l++) {
            int idx = tid + l * 256;
            int mat = idx >> 9;                 // 0:Kh 1:Kl 2:Vh 3:Vl
            int r = (idx >> 3) & 63, cc = idx & 7;
            const __nv_bfloat16* gsrc = (mat & 1) ? qkvl : qkvh;
            long base = (mat >= 2) ? vbase : kbase;
            cp16(sb + mat * TWORDS + r * ASTR + cc * 4,
                 gsrc + base + (long)(k0 + r) * E_ + cc * 8);
        }
        cp_commit();
    };

    issueKV(0, 0);
    issueKV(1, 1);

    float O[8][4];
#pragma unroll
    for (int nt = 0; nt < 8; nt++)
#pragma unroll
        for (int e = 0; e < 4; e++) O[nt][e] = 0.f;
    float m0v = -INFINITY, m1v = -INFINITY, l0v = 0.f, l1v = 0.f;

    for (int jb = 0; jb < njb; jb++) {
        const int st = jb & 1;
        const int k0 = jb * 64;
        if (jb + 1 < njb) cp_wait1(); else cp_wait0();
        __syncthreads();

        const bool active = (k0 <= wrow0 + 15);
        if (active) {
            unsigned* sb = asmem + 2 * QWORDS + st * ATTN_STAGE_WORDS;
            unsigned* Kh = sb;
            unsigned* Kl = sb + TWORDS;
            unsigned* Vh = sb + 2 * TWORDS;
            unsigned* Vl = sb + 3 * TWORDS;

            // S = Q K^T
            float S[8][4];
#pragma unroll
            for (int nt = 0; nt < 8; nt++)
#pragma unroll
                for (int e = 0; e < 4; e++) S[nt][e] = 0.f;

#pragma unroll
            for (int s = 0; s < 4; s++) {
                unsigned qh4[4], ql4[4];
                {
                    int row = warp * 16 + (lane & 15);
                    int kw  = s * 8 + ((lane >> 4) << 2);
                    ldmx4(qh4, Qh + row * ASTR + kw);
                    ldmx4(ql4, Ql + row * ASTR + kw);
                }
#pragma unroll
                for (int ntp = 0; ntp < 4; ntp++) {
                    int row = ntp * 16 + ((lane >> 4) << 3) + (lane & 7);
                    int kw  = s * 8 + ((lane & 8) >> 1);
                    unsigned kh4[4], kl4[4];
                    ldmx4(kh4, Kh + row * ASTR + kw);
                    ldmx4(kl4, Kl + row * ASTR + kw);
                    unsigned kh0[2] = { kh4[0], kh4[1] }, kl0[2] = { kl4[0], kl4[1] };
                    unsigned kh1[2] = { kh4[2], kh4[3] }, kl1[2] = { kl4[2], kl4[3] };
                    mma16816(S[2 * ntp],     qh4, kh0);
                    mma16816(S[2 * ntp],     qh4, kl0);
                    mma16816(S[2 * ntp],     ql4, kh0);
                    mma16816(S[2 * ntp + 1], qh4, kh1);
                    mma16816(S[2 * ntp + 1], qh4, kl1);
                    mma16816(S[2 * ntp + 1], ql4, kh1);
                }
            }

            const float sc = 0.125f;
            if (k0 + 63 > wrow0) {      // diagonal tile for this warp
#pragma unroll
                for (int nt = 0; nt < 8; nt++)
#pragma unroll
                    for (int e = 0; e < 4; e++) {
                        int r = wrow0 + rw + ((e >= 2) ? 8 : 0);
                        int c = k0 + nt * 8 + cw * 2 + (e & 1);
                        S[nt][e] = (c <= r) ? S[nt][e] * sc : -1e30f;
                    }
            } else {
#pragma unroll
                for (int nt = 0; nt < 8; nt++)
#pragma unroll
                    for (int e = 0; e < 4; e++) S[nt][e] *= sc;
            }

            // online softmax
            float mx0 = -INFINITY, mx1 = -INFINITY;
#pragma unroll
            for (int nt = 0; nt < 8; nt++) {
                mx0 = fmaxf(mx0, fmaxf(S[nt][0], S[nt][1]));
                mx1 = fmaxf(mx1, fmaxf(S[nt][2], S[nt][3]));
            }
            mx0 = fmaxf(mx0, __shfl_xor_sync(0xffffffff, mx0, 1));
            mx0 = fmaxf(mx0, __shfl_xor_sync(0xffffffff, mx0, 2));
            mx1 = fmaxf(mx1, __shfl_xor_sync(0xffffffff, mx1, 1));
            mx1 = fmaxf(mx1, __shfl_xor_sync(0xffffffff, mx1, 2));
            float mn0 = fmaxf(m0v, mx0), mn1 = fmaxf(m1v, mx1);
            float a0 = exp2f((m0v - mn0) * LOG2E), a1 = exp2f((m1v - mn1) * LOG2E);
            m0v = mn0; m1v = mn1;
            float sum0 = 0.f, sum1 = 0.f;
#pragma unroll
            for (int nt = 0; nt < 8; nt++) {
                float p0 = exp2f((S[nt][0] - mn0) * LOG2E);
                float p1 = exp2f((S[nt][1] - mn0) * LOG2E);
                float p2 = exp2f((S[nt][2] - mn1) * LOG2E);
                float p3 = exp2f((S[nt][3] - mn1) * LOG2E);
                S[nt][0] = p0; S[nt][1] = p1; S[nt][2] = p2; S[nt][3] = p3;
                sum0 += p0 + p1; sum1 += p2 + p3;
            }
            sum0 += __shfl_xor_sync(0xffffffff, sum0, 1);
            sum0 += __shfl_xor_sync(0xffffffff, sum0, 2);
            sum1 += __shfl_xor_sync(0xffffffff, sum1, 1);
            sum1 += __shfl_xor_sync(0xffffffff, sum1, 2);
            l0v = l0v * a0 + sum0;
            l1v = l1v * a1 + sum1;
#pragma unroll
            for (int nt = 0; nt < 8; nt++) {
                O[nt][0] *= a0; O[nt][1] *= a0;
                O[nt][2] *= a1; O[nt][3] *= a1;
            }

            // O += P V
#pragma unroll
            for (int s = 0; s < 4; s++) {
                const int j0 = 2 * s, j1 = 2 * s + 1;
                unsigned ph[4], pl[4];
                ph[0] = pack2(S[j0][0], S[j0][1]);
                ph[1] = pack2(S[j0][2], S[j0][3]);
                ph[2] = pack2(S[j1][0], S[j1][1]);
                ph[3] = pack2(S[j1][2], S[j1][3]);
                pl[0] = pack2(resid(S[j0][0]), resid(S[j0][1]));
                pl[1] = pack2(resid(S[j0][2]), resid(S[j0][3]));
                pl[2] = pack2(resid(S[j1][0]), resid(S[j1][1]));
                pl[3] = pack2(resid(S[j1][2]), resid(S[j1][3]));
#pragma unroll
                for (int dt = 0; dt < 4; dt++) {
                    int vrow = s * 16 + (lane & 15);
                    int nb   = dt * 16 + ((lane >> 4) << 3);
                    unsigned vh4[4], vl4[4];
                    ldmx4t(vh4, Vh + vrow * ASTR + (nb >> 1));
                    ldmx4t(vl4, Vl + vrow * ASTR + (nb >> 1));
                    unsigned bh0[2] = { vh4[0], vh4[1] }, bl0[2] = { vl4[0], vl4[1] };
                    unsigned bh1[2] = { vh4[2], vh4[3] }, bl1[2] = { vl4[2], vl4[3] };
                    mma16816(O[2 * dt], ph, bh0);
                    mma16816(O[2 * dt], ph, bl0);
                    mma16816(O[2 * dt], pl, bh0);
                    mma16816(O[2 * dt + 1], ph, bh1);
                    mma16816(O[2 * dt + 1], ph, bl1);
                    mma16816(O[2 * dt + 1], pl, bh1);
                }
            }
        }
        __syncthreads();
        if (jb + 2 < njb) issueKV(jb + 2, st);
    }

    // epilogue: normalize and write split bf16
    float i0 = 1.f / l0v, i1 = 1.f / l1v;
    long row = (long)(b * T_ + wrow0 + rw);
    long colb = h * HD_ + cw * 2;
#pragma unroll
    for (int nt = 0; nt < 8; nt++) {
        float o0 = O[nt][0] * i0, o1 = O[nt][1] * i0;
        float o2 = O[nt][2] * i1, o3 = O[nt][3] * i1;
        long p0 = row * D_ + colb + nt * 8;
        long p1 = (row + 8) * D_ + colb + nt * 8;
        *(unsigned*)(oh + p0) = pack2(o0, o1);
        *(unsigned*)(ol + p0) = pack2(resid(o0), resid(o1));
        *(unsigned*)(oh + p1) = pack2(o2, o3);
        *(unsigned*)(ol + p1) = pack2(resid(o2), resid(o3));
    }
}

// ---------------------------------------------------------------------------
// Launch
// ---------------------------------------------------------------------------
extern "C" void kernel_launch(void* const* d_in, const int* in_sizes, int n_in,
                              void* d_out, int out_size)
{
    const float* x     = (const float*)d_in[0];
    const float* sinb  = (const float*)d_in[1];
    const float* cosb  = (const float*)d_in[2];
    const float* w_qkv = (const float*)d_in[3];
    const float* w_out = (const float*)d_in[4];
    float* out = (float*)d_out;

    __nv_bfloat16 *xh, *xl, *qh, *ql, *ath, *atl, *wqh, *wql, *woh, *wol;
    cudaGetSymbolAddress((void**)&xh, g_xh);
    cudaGetSymbolAddress((void**)&xl, g_xl);
    cudaGetSymbolAddress((void**)&qh, g_qkvh);
    cudaGetSymbolAddress((void**)&ql, g_qkvl);
    cudaGetSymbolAddress((void**)&ath, g_ath);
    cudaGetSymbolAddress((void**)&atl, g_atl);
    cudaGetSymbolAddress((void**)&wqh, g_wqkv_h);
    cudaGetSymbolAddress((void**)&wql, g_wqkv_l);
    cudaGetSymbolAddress((void**)&woh, g_wout_h);
    cudaGetSymbolAddress((void**)&wol, g_wout_l);

    const int gemm_smem = 2 * STAGE_U32 * 4;   // 81920 B -> 2 CTAs/SM
    const int attn_smem = ATTN_SMEM_BYTES;     // 110592 B
    cudaFuncSetAttribute(gemm_bf16x3, cudaFuncAttributeMaxDynamicSharedMemorySize, gemm_smem);
    cudaFuncSetAttribute(attn_mma, cudaFuncAttributeMaxDynamicSharedMemorySize, attn_smem);

    // 0) splits
    xsplit_kernel<<<(BT_ * D_ / 4 + 255) / 256, 256>>>(x, xh, xl);
    wsplit_kernel<<<dim3(E_ / 32, D_ / 32), dim3(32, 8)>>>(w_qkv, wqh, wql, D_, E_);
    wsplit_kernel<<<dim3(D_ / 32, D_ / 32), dim3(32, 8)>>>(w_out, woh, wol, D_, D_);

    // 1) QKV projection with fused RoPE + split epilogue
    gemm_bf16x3<<<dim3(E_ / 128, BT_ / 128), 256, gemm_smem>>>(
        xh, xl, wqh, wql, nullptr, BT_, E_, D_, 1, sinb, cosb, qh, ql);

    // 2) Flash attention (q-tile 128)
    attn_mma<<<dim3(T_ / 128, NH_, B_), 256, attn_smem>>>(qh, ql, ath, atl);

    // 3) Output projection (fp32 epilogue)
    gemm_bf16x3<<<dim3(D_ / 128, BT_ / 128), 256, gemm_smem>>>(
        ath, atl, woh, wol, out, BT_, D_, D_, 0, nullptr, nullptr, nullptr, nullptr);
}

// round 9
// speedup vs baseline: 3.5294x; 1.0996x over previous
#include <cuda_runtime.h>
#include <cuda_bf16.h>
#include <math.h>

// Problem constants
#define B_  2
#define T_  2048
#define D_  2048
#define E_  3072          // D + 2*KV_DIM
#define KV_ 512
#define HD_ 64
#define NH_ 32
#define BT_ 4096          // B*T

#define LOG2E 1.4426950408889634f

// Scratch (static __device__ arrays; allocation-free rule)
__device__ __nv_bfloat16 g_xh[BT_ * D_],  g_xl[BT_ * D_];    // x split
__device__ __nv_bfloat16 g_qkvh[BT_ * E_], g_qkvl[BT_ * E_]; // roped qkv split
__device__ __nv_bfloat16 g_ath[BT_ * D_], g_atl[BT_ * D_];   // attn out split
__device__ __nv_bfloat16 g_wqkv_h[E_ * D_], g_wqkv_l[E_ * D_];
__device__ __nv_bfloat16 g_wout_h[D_ * D_], g_wout_l[D_ * D_];

// ---------------------------------------------------------------------------
// helpers
// ---------------------------------------------------------------------------
__device__ __forceinline__ unsigned pack2(float x, float y) {
    __nv_bfloat162 h = __floats2bfloat162_rn(x, y);   // .x in low half
    return *(unsigned*)&h;
}
__device__ __forceinline__ float resid(float x) {
    return x - __bfloat162float(__float2bfloat16_rn(x));
}
__device__ __forceinline__ void mma16816(float c[4], const unsigned a[4], const unsigned b[2]) {
    asm volatile(
        "mma.sync.aligned.m16n8k16.row.col.f32.bf16.bf16.f32 "
        "{%0,%1,%2,%3},{%4,%5,%6,%7},{%8,%9},{%0,%1,%2,%3};\n"
        : "+f"(c[0]), "+f"(c[1]), "+f"(c[2]), "+f"(c[3])
        : "r"(a[0]), "r"(a[1]), "r"(a[2]), "r"(a[3]), "r"(b[0]), "r"(b[1]));
}
__device__ __forceinline__ void cp16(void* dst_smem, const void* src) {
    unsigned d = (unsigned)__cvta_generic_to_shared(dst_smem);
    asm volatile("cp.async.cg.shared.global [%0], [%1], 16;\n" :: "r"(d), "l"(src));
}
__device__ __forceinline__ void cp_commit() { asm volatile("cp.async.commit_group;\n" ::: "memory"); }
__device__ __forceinline__ void cp_wait0()  { asm volatile("cp.async.wait_group 0;\n" ::: "memory"); }
__device__ __forceinline__ void cp_wait1()  { asm volatile("cp.async.wait_group 1;\n" ::: "memory"); }
__device__ __forceinline__ void ldmx4(unsigned r[4], const void* p) {
    unsigned a = (unsigned)__cvta_generic_to_shared(p);
    asm volatile("ldmatrix.sync.aligned.m8n8.x4.shared.b16 {%0,%1,%2,%3},[%4];\n"
                 : "=r"(r[0]), "=r"(r[1]), "=r"(r[2]), "=r"(r[3]) : "r"(a));
}
__device__ __forceinline__ void ldmx4t(unsigned r[4], const void* p) {
    unsigned a = (unsigned)__cvta_generic_to_shared(p);
    asm volatile("ldmatrix.sync.aligned.m8n8.x4.trans.shared.b16 {%0,%1,%2,%3},[%4];\n"
                 : "=r"(r[0]), "=r"(r[1]), "=r"(r[2]), "=r"(r[3]) : "r"(a));
}

// ---------------------------------------------------------------------------
// x split: fp32 -> bf16 hi/lo
// ---------------------------------------------------------------------------
__global__ void xsplit_kernel(const float* __restrict__ X,
                              __nv_bfloat16* __restrict__ Xh,
                              __nv_bfloat16* __restrict__ Xl)
{
    long i = (long)(blockIdx.x * blockDim.x + threadIdx.x) * 4;
    if (i >= (long)BT_ * D_) return;
    float4 v = *(const float4*)(X + i);
    unsigned h0 = pack2(v.x, v.y), h1 = pack2(v.z, v.w);
    unsigned l0 = pack2(resid(v.x), resid(v.y)), l1 = pack2(resid(v.z), resid(v.w));
    *(uint2*)(Xh + i) = make_uint2(h0, h1);
    *(uint2*)(Xl + i) = make_uint2(l0, l1);
}

// ---------------------------------------------------------------------------
// Weight split+transpose: W[K][N] fp32 -> Wt_hi/Wt_lo [N][K] bf16
// ---------------------------------------------------------------------------
__global__ void wsplit_kernel(const float* __restrict__ W,
                              __nv_bfloat16* __restrict__ Oh,
                              __nv_bfloat16* __restrict__ Ol, int K, int N)
{
    __shared__ float t[32][33];
    int n0 = blockIdx.x * 32, k0 = blockIdx.y * 32;
    for (int i = threadIdx.y; i < 32; i += 8)
        t[i][threadIdx.x] = W[(long)(k0 + i) * N + n0 + threadIdx.x];
    __syncthreads();
    for (int i = threadIdx.y; i < 32; i += 8) {
        float v = t[threadIdx.x][i];
        long o = (long)(n0 + i) * K + k0 + threadIdx.x;
        __nv_bfloat16 h = __float2bfloat16_rn(v);
        Oh[o] = h;
        Ol[o] = __float2bfloat16_rn(v - __bfloat162float(h));
    }
}

// ---------------------------------------------------------------------------
// GEMM (bf16x3, mma.sync): C[M,N] = A[M,K] * W[K,N]
// A pre-split [M][K] bf16 hi/lo; W pre-split/transposed [N][K] bf16 hi/lo.
// 128x128x32 tiles, 256 threads, warptile 32x64.
// XOR-swizzled unpadded smem rows (64 B, 4 chunks; chunk ^= (row>>1)&3),
// 3-stage cp.async ring @ 32 KB/stage -> 96 KB total -> 2 CTAs/SM,
// ONE __syncthreads per k-block; loads issued before MMAs.
// mode 0: write C fp32.  mode 1: fused RoPE + bf16 hi/lo split -> Ch/Cl.
// ---------------------------------------------------------------------------
#define GMAT 8192                 // bytes per matrix tile (128 rows x 64 B)
#define GSTAGE (4 * GMAT)         // Ah,Al,Bh,Bl = 32768 B
#define GEMM_SMEM (3 * GSTAGE)    // 98304 B

__global__ void __launch_bounds__(256, 2) gemm_bf16x3(
    const __nv_bfloat16* __restrict__ Ah_g, const __nv_bfloat16* __restrict__ Al_g,
    const __nv_bfloat16* __restrict__ Bh_g, const __nv_bfloat16* __restrict__ Bl_g,
    float* __restrict__ C, int M, int N, int K, int mode,
    const float* __restrict__ sinb, const float* __restrict__ cosb,
    __nv_bfloat16* __restrict__ Ch, __nv_bfloat16* __restrict__ Cl)
{
    extern __shared__ __align__(128) char gsm[];
    const int tid = threadIdx.x, lane = tid & 31, warp = tid >> 5;
    const int row0 = blockIdx.y * 128, col0 = blockIdx.x * 128;
    const int m0 = (warp >> 1) * 32, n0w = (warp & 1) * 64;
    const int rw = lane >> 2, cw = lane & 3;
    const int nk = K >> 5;

    float acc[2][8][4];
#pragma unroll
    for (int mt = 0; mt < 2; mt++)
#pragma unroll
        for (int nt = 0; nt < 8; nt++)
#pragma unroll
            for (int e = 0; e < 4; e++) acc[mt][nt][e] = 0.f;

    auto issue = [&](int st, int kb) {
        char* base = gsm + st * GSTAGE;
#pragma unroll
        for (int l = 0; l < 8; l++) {
            int idx = tid + l * 256;               // 0..2047
            int mat = idx >> 9;                    // 0:Ah 1:Al 2:Bh 3:Bl
            int r   = (idx >> 2) & 127;
            int c   = idx & 3;                     // logical 16B chunk
            const __nv_bfloat16* g = (mat == 0) ? Ah_g : (mat == 1) ? Al_g
                                   : (mat == 2) ? Bh_g : Bl_g;
            long grow = (long)((mat < 2 ? row0 : col0) + r);
            cp16(base + mat * GMAT + r * 64 + ((c ^ ((r >> 1) & 3)) << 4),
                 g + grow * K + kb * 32 + c * 8);
        }
        cp_commit();
    };

    issue(0, 0);
    if (nk > 1) issue(1, 1);

    for (int kb = 0; kb < nk; kb++) {
        const int st = kb % 3;
        if (kb + 1 < nk) cp_wait1(); else cp_wait0();
        __syncthreads();
        if (kb + 2 < nk) issue((kb + 2) % 3, kb + 2);   // into stage free since last iter

        char* base = gsm + st * GSTAGE;
#pragma unroll
        for (int s = 0; s < 2; s++) {
            unsigned ah[2][4], al[2][4];
#pragma unroll
            for (int mt = 0; mt < 2; mt++) {
                int row = m0 + mt * 16 + (lane & 15);
                int ch  = 2 * s + (lane >> 4);
                int off = row * 64 + ((ch ^ ((row >> 1) & 3)) << 4);
                ldmx4(ah[mt], base + off);
                ldmx4(al[mt], base + GMAT + off);
            }
#pragma unroll
            for (int ntp = 0; ntp < 4; ntp++) {
                int row = n0w + ntp * 16 + ((lane >> 4) << 3) + (lane & 7);
                int ch  = 2 * s + ((lane & 8) >> 3);
                int off = row * 64 + ((ch ^ ((row >> 1) & 3)) << 4);
                unsigned bh4[4], bl4[4];
                ldmx4(bh4, base + 2 * GMAT + off);
                ldmx4(bl4, base + 3 * GMAT + off);
                unsigned bh0[2] = { bh4[0], bh4[1] }, bl0[2] = { bl4[0], bl4[1] };
                unsigned bh1[2] = { bh4[2], bh4[3] }, bl1[2] = { bl4[2], bl4[3] };
#pragma unroll
                for (int mt = 0; mt < 2; mt++) {
                    mma16816(acc[mt][2 * ntp],     ah[mt], bh0);
                    mma16816(acc[mt][2 * ntp],     ah[mt], bl0);
                    mma16816(acc[mt][2 * ntp],     al[mt], bh0);
                    mma16816(acc[mt][2 * ntp + 1], ah[mt], bh1);
                    mma16816(acc[mt][2 * ntp + 1], ah[mt], bl1);
                    mma16816(acc[mt][2 * ntp + 1], al[mt], bh1);
                }
            }
        }
    }

    // ---- epilogue
    if (mode == 0) {
#pragma unroll
        for (int mt = 0; mt < 2; mt++) {
#pragma unroll
            for (int nt = 0; nt < 8; nt++) {
                int row = row0 + m0 + mt * 16 + rw;
                int col = col0 + n0w + nt * 8 + cw * 2;
                *(float2*)(C + (long)row * N + col)       = make_float2(acc[mt][nt][0], acc[mt][nt][1]);
                *(float2*)(C + (long)(row + 8) * N + col) = make_float2(acc[mt][nt][2], acc[mt][nt][3]);
            }
        }
    } else {
        const bool isv = (col0 + n0w) >= (D_ + KV_);
#pragma unroll
        for (int mt = 0; mt < 2; mt++) {
            int rbase = row0 + m0 + mt * 16 + rw;
#pragma unroll
            for (int half = 0; half < 2; half++) {
                int r = rbase + half * 8;
                int t = r & (T_ - 1);
                if (!isv) {
#pragma unroll
                    for (int nt = 0; nt < 4; nt++) {
                        float ol0[2], ol1[2];
#pragma unroll
                        for (int d = 0; d < 2; d++) {
                            int e = half * 2 + d;
                            float u1 = acc[mt][nt][e];
                            float u2 = acc[mt][nt + 4][e];
                            int i = nt * 8 + cw * 2 + d;
                            float c1 = cosb[t * HD_ + i],      s1 = sinb[t * HD_ + i];
                            float c2 = cosb[t * HD_ + i + 32], s2 = sinb[t * HD_ + i + 32];
                            ol0[d] = u1 * c1 - u2 * s1;
                            ol1[d] = u2 * c2 + u1 * s2;
                        }
                        long p = (long)r * E_ + col0 + n0w + nt * 8 + cw * 2;
                        *(unsigned*)(Ch + p)      = pack2(ol0[0], ol0[1]);
                        *(unsigned*)(Cl + p)      = pack2(resid(ol0[0]), resid(ol0[1]));
                        *(unsigned*)(Ch + p + 32) = pack2(ol1[0], ol1[1]);
                        *(unsigned*)(Cl + p + 32) = pack2(resid(ol1[0]), resid(ol1[1]));
                    }
                } else {
#pragma unroll
                    for (int nt = 0; nt < 8; nt++) {
                        float v0 = acc[mt][nt][half * 2];
                        float v1 = acc[mt][nt][half * 2 + 1];
                        long p = (long)r * E_ + col0 + n0w + nt * 8 + cw * 2;
                        *(unsigned*)(Ch + p) = pack2(v0, v1);
                        *(unsigned*)(Cl + p) = pack2(resid(v0), resid(v1));
                    }
                }
            }
        }
    }
}

// ---------------------------------------------------------------------------
// Flash attention (causal, GQA), mma.sync. 256 threads (8 warps), q-tile 128
// rows (16 per warp). K/V tiles 64 rows, double-buffered cp.async.
// XOR-swizzled unpadded smem rows (128 B, 8 chunks; chunk ^= row&7):
// Q 32 KB + 2 KV stages x 32 KB = 96 KB -> 2 CTAs/SM.
// ---------------------------------------------------------------------------
#define AMAT_Q 16384              // 128 rows x 128 B
#define AMAT_KV 8192              // 64 rows x 128 B
#define ASTAGE (4 * AMAT_KV)      // Kh,Kl,Vh,Vl = 32768 B
#define ATTN_SMEM (2 * AMAT_Q + 2 * ASTAGE)   // 98304 B

__global__ void __launch_bounds__(256, 2) attn_mma(
    const __nv_bfloat16* __restrict__ qkvh, const __nv_bfloat16* __restrict__ qkvl,
    __nv_bfloat16* __restrict__ oh, __nv_bfloat16* __restrict__ ol)
{
    extern __shared__ __align__(128) char asm_[];
    const int tid = threadIdx.x, lane = tid & 31, warp = tid >> 5;
    const int qb = blockIdx.x, h = blockIdx.y, b = blockIdx.z;
    const int q0 = qb * 128;
    const int rw = lane >> 2, cw = lane & 3;
    const int wrow0 = q0 + warp * 16;

    const long qbase = (long)(b * T_) * E_ + h * HD_;
    const long kbase = (long)(b * T_) * E_ + D_ + (h >> 2) * HD_;
    const long vbase = kbase + KV_;

    // issue Q (one cp.async group): 2 mats x 128 rows x 8 chunks = 2048
#pragma unroll
    for (int l = 0; l < 8; l++) {
        int idx = tid + l * 256;
        int mat = idx >> 10, r = (idx >> 3) & 127, c = idx & 7;
        const __nv_bfloat16* src = (mat ? qkvl : qkvh) + qbase + (long)(q0 + r) * E_ + c * 8;
        cp16(asm_ + mat * AMAT_Q + r * 128 + ((c ^ (r & 7)) << 4), src);
    }
    cp_commit();

    const int njb = 2 * qb + 2;

    auto issueKV = [&](int jb, int st) {
        char* sb = asm_ + 2 * AMAT_Q + st * ASTAGE;
        const int k0 = jb * 64;
#pragma unroll
        for (int l = 0; l < 8; l++) {
            int idx = tid + l * 256;
            int mat = idx >> 9;                 // 0:Kh 1:Kl 2:Vh 3:Vl
            int r = (idx >> 3) & 63, c = idx & 7;
            const __nv_bfloat16* gsrc = (mat & 1) ? qkvl : qkvh;
            long base = (mat >= 2) ? vbase : kbase;
            cp16(sb + mat * AMAT_KV + r * 128 + ((c ^ (r & 7)) << 4),
                 gsrc + base + (long)(k0 + r) * E_ + c * 8);
        }
        cp_commit();
    };

    issueKV(0, 0);
    issueKV(1, 1);

    float O[8][4];
#pragma unroll
    for (int nt = 0; nt < 8; nt++)
#pragma unroll
        for (int e = 0; e < 4; e++) O[nt][e] = 0.f;
    float m0v = -INFINITY, m1v = -INFINITY, l0v = 0.f, l1v = 0.f;

    for (int jb = 0; jb < njb; jb++) {
        const int st = jb & 1;
        const int k0 = jb * 64;
        if (jb + 1 < njb) cp_wait1(); else cp_wait0();
        __syncthreads();

        const bool active = (k0 <= wrow0 + 15);
        if (active) {
            char* sb = asm_ + 2 * AMAT_Q + st * ASTAGE;

            // S = Q K^T
            float S[8][4];
#pragma unroll
            for (int nt = 0; nt < 8; nt++)
#pragma unroll
                for (int e = 0; e < 4; e++) S[nt][e] = 0.f;

#pragma unroll
            for (int s = 0; s < 4; s++) {
                unsigned qh4[4], ql4[4];
                {
                    int row = warp * 16 + (lane & 15);
                    int ch  = 2 * s + (lane >> 4);
                    int off = row * 128 + ((ch ^ (row & 7)) << 4);
                    ldmx4(qh4, asm_ + off);
                    ldmx4(ql4, asm_ + AMAT_Q + off);
                }
#pragma unroll
                for (int ntp = 0; ntp < 4; ntp++) {
                    int row = ntp * 16 + ((lane >> 4) << 3) + (lane & 7);
                    int ch  = 2 * s + ((lane & 8) >> 3);
                    int off = row * 128 + ((ch ^ (row & 7)) << 4);
                    unsigned kh4[4], kl4[4];
                    ldmx4(kh4, sb + off);
                    ldmx4(kl4, sb + AMAT_KV + off);
                    unsigned kh0[2] = { kh4[0], kh4[1] }, kl0[2] = { kl4[0], kl4[1] };
                    unsigned kh1[2] = { kh4[2], kh4[3] }, kl1[2] = { kl4[2], kl4[3] };
                    mma16816(S[2 * ntp],     qh4, kh0);
                    mma16816(S[2 * ntp],     qh4, kl0);
                    mma16816(S[2 * ntp],     ql4, kh0);
                    mma16816(S[2 * ntp + 1], qh4, kh1);
                    mma16816(S[2 * ntp + 1], qh4, kl1);
                    mma16816(S[2 * ntp + 1], ql4, kh1);
                }
            }

            const float sc = 0.125f;
            if (k0 + 63 > wrow0) {      // diagonal tile for this warp
#pragma unroll
                for (int nt = 0; nt < 8; nt++)
#pragma unroll
                    for (int e = 0; e < 4; e++) {
                        int r = wrow0 + rw + ((e >= 2) ? 8 : 0);
                        int c = k0 + nt * 8 + cw * 2 + (e & 1);
                        S[nt][e] = (c <= r) ? S[nt][e] * sc : -1e30f;
                    }
            } else {
#pragma unroll
                for (int nt = 0; nt < 8; nt++)
#pragma unroll
                    for (int e = 0; e < 4; e++) S[nt][e] *= sc;
            }

            // online softmax
            float mx0 = -INFINITY, mx1 = -INFINITY;
#pragma unroll
            for (int nt = 0; nt < 8; nt++) {
                mx0 = fmaxf(mx0, fmaxf(S[nt][0], S[nt][1]));
                mx1 = fmaxf(mx1, fmaxf(S[nt][2], S[nt][3]));
            }
            mx0 = fmaxf(mx0, __shfl_xor_sync(0xffffffff, mx0, 1));
            mx0 = fmaxf(mx0, __shfl_xor_sync(0xffffffff, mx0, 2));
            mx1 = fmaxf(mx1, __shfl_xor_sync(0xffffffff, mx1, 1));
            mx1 = fmaxf(mx1, __shfl_xor_sync(0xffffffff, mx1, 2));
            float mn0 = fmaxf(m0v, mx0), mn1 = fmaxf(m1v, mx1);
            float a0 = exp2f((m0v - mn0) * LOG2E), a1 = exp2f((m1v - mn1) * LOG2E);
            m0v = mn0; m1v = mn1;
            float sum0 = 0.f, sum1 = 0.f;
#pragma unroll
            for (int nt = 0; nt < 8; nt++) {
                float p0 = exp2f((S[nt][0] - mn0) * LOG2E);
                float p1 = exp2f((S[nt][1] - mn0) * LOG2E);
                float p2 = exp2f((S[nt][2] - mn1) * LOG2E);
                float p3 = exp2f((S[nt][3] - mn1) * LOG2E);
                S[nt][0] = p0; S[nt][1] = p1; S[nt][2] = p2; S[nt][3] = p3;
                sum0 += p0 + p1; sum1 += p2 + p3;
            }
            sum0 += __shfl_xor_sync(0xffffffff, sum0, 1);
            sum0 += __shfl_xor_sync(0xffffffff, sum0, 2);
            sum1 += __shfl_xor_sync(0xffffffff, sum1, 1);
            sum1 += __shfl_xor_sync(0xffffffff, sum1, 2);
            l0v = l0v * a0 + sum0;
            l1v = l1v * a1 + sum1;
#pragma unroll
            for (int nt = 0; nt < 8; nt++) {
                O[nt][0] *= a0; O[nt][1] *= a0;
                O[nt][2] *= a1; O[nt][3] *= a1;
            }

            // O += P V
#pragma unroll
            for (int s = 0; s < 4; s++) {
                const int j0 = 2 * s, j1 = 2 * s + 1;
                unsigned ph_[4], pl_[4];
                ph_[0] = pack2(S[j0][0], S[j0][1]);
                ph_[1] = pack2(S[j0][2], S[j0][3]);
                ph_[2] = pack2(S[j1][0], S[j1][1]);
                ph_[3] = pack2(S[j1][2], S[j1][3]);
                pl_[0] = pack2(resid(S[j0][0]), resid(S[j0][1]));
                pl_[1] = pack2(resid(S[j0][2]), resid(S[j0][3]));
                pl_[2] = pack2(resid(S[j1][0]), resid(S[j1][1]));
                pl_[3] = pack2(resid(S[j1][2]), resid(S[j1][3]));
#pragma unroll
                for (int dt = 0; dt < 4; dt++) {
                    int vrow = s * 16 + (lane & 15);
                    int ch   = 2 * dt + (lane >> 4);
                    int off  = vrow * 128 + ((ch ^ (vrow & 7)) << 4);
                    unsigned vh4[4], vl4[4];
                    ldmx4t(vh4, sb + 2 * AMAT_KV + off);
                    ldmx4t(vl4, sb + 3 * AMAT_KV + off);
                    unsigned bh0[2] = { vh4[0], vh4[1] }, bl0[2] = { vl4[0], vl4[1] };
                    unsigned bh1[2] = { vh4[2], vh4[3] }, bl1[2] = { vl4[2], vl4[3] };
                    mma16816(O[2 * dt], ph_, bh0);
                    mma16816(O[2 * dt], ph_, bl0);
                    mma16816(O[2 * dt], pl_, bh0);
                    mma16816(O[2 * dt + 1], ph_, bh1);
                    mma16816(O[2 * dt + 1], ph_, bl1);
                    mma16816(O[2 * dt + 1], pl_, bh1);
                }
            }
        }
        __syncthreads();
        if (jb + 2 < njb) issueKV(jb + 2, st);
    }

    // epilogue: normalize and write split bf16
    float i0 = 1.f / l0v, i1 = 1.f / l1v;
    long row = (long)(b * T_ + wrow0 + rw);
    long colb = h * HD_ + cw * 2;
#pragma unroll
    for (int nt = 0; nt < 8; nt++) {
        float o0 = O[nt][0] * i0, o1 = O[nt][1] * i0;
        float o2 = O[nt][2] * i1, o3 = O[nt][3] * i1;
        long p0 = row * D_ + colb + nt * 8;
        long p1 = (row + 8) * D_ + colb + nt * 8;
        *(unsigned*)(oh + p0) = pack2(o0, o1);
        *(unsigned*)(ol + p0) = pack2(resid(o0), resid(o1));
        *(unsigned*)(oh + p1) = pack2(o2, o3);
        *(unsigned*)(ol + p1) = pack2(resid(o2), resid(o3));
    }
}

// ---------------------------------------------------------------------------
// Launch
// ---------------------------------------------------------------------------
extern "C" void kernel_launch(void* const* d_in, const int* in_sizes, int n_in,
                              void* d_out, int out_size)
{
    const float* x     = (const float*)d_in[0];
    const float* sinb  = (const float*)d_in[1];
    const float* cosb  = (const float*)d_in[2];
    const float* w_qkv = (const float*)d_in[3];
    const float* w_out = (const float*)d_in[4];
    float* out = (float*)d_out;

    __nv_bfloat16 *xh, *xl, *qh, *ql, *ath, *atl, *wqh, *wql, *woh, *wol;
    cudaGetSymbolAddress((void**)&xh, g_xh);
    cudaGetSymbolAddress((void**)&xl, g_xl);
    cudaGetSymbolAddress((void**)&qh, g_qkvh);
    cudaGetSymbolAddress((void**)&ql, g_qkvl);
    cudaGetSymbolAddress((void**)&ath, g_ath);
    cudaGetSymbolAddress((void**)&atl, g_atl);
    cudaGetSymbolAddress((void**)&wqh, g_wqkv_h);
    cudaGetSymbolAddress((void**)&wql, g_wqkv_l);
    cudaGetSymbolAddress((void**)&woh, g_wout_h);
    cudaGetSymbolAddress((void**)&wol, g_wout_l);

    cudaFuncSetAttribute(gemm_bf16x3, cudaFuncAttributeMaxDynamicSharedMemorySize, GEMM_SMEM);
    cudaFuncSetAttribute(attn_mma, cudaFuncAttributeMaxDynamicSharedMemorySize, ATTN_SMEM);

    // 0) splits
    xsplit_kernel<<<(BT_ * D_ / 4 + 255) / 256, 256>>>(x, xh, xl);
    wsplit_kernel<<<dim3(E_ / 32, D_ / 32), dim3(32, 8)>>>(w_qkv, wqh, wql, D_, E_);
    wsplit_kernel<<<dim3(D_ / 32, D_ / 32), dim3(32, 8)>>>(w_out, woh, wol, D_, D_);

    // 1) QKV projection with fused RoPE + split epilogue
    gemm_bf16x3<<<dim3(E_ / 128, BT_ / 128), 256, GEMM_SMEM>>>(
        xh, xl, wqh, wql, nullptr, BT_, E_, D_, 1, sinb, cosb, qh, ql);

    // 2) Flash attention (q-tile 128)
    attn_mma<<<dim3(T_ / 128, NH_, B_), 256, ATTN_SMEM>>>(qh, ql, ath, atl);

    // 3) Output projection (fp32 epilogue)
    gemm_bf16x3<<<dim3(D_ / 128, BT_ / 128), 256, GEMM_SMEM>>>(
        ath, atl, woh, wol, out, BT_, D_, D_, 0, nullptr, nullptr, nullptr, nullptr);
}

// round 10
// speedup vs baseline: 4.8485x; 1.3737x over previous
#include <cuda_runtime.h>
#include <cuda_fp16.h>
#include <math.h>

// Problem constants
#define B_  2
#define T_  2048
#define D_  2048
#define E_  3072          // D + 2*KV_DIM
#define KV_ 512
#define HD_ 64
#define NH_ 32
#define BT_ 4096          // B*T

#define LOG2E 1.4426950408889634f

// Scratch (static __device__ arrays; allocation-free rule)
__device__ __half g_xh[BT_ * D_];                       // x hi (left operand only)
__device__ __half g_qkvh[BT_ * E_], g_qkvl[BT_ * E_];   // roped qkv hi/lo
__device__ __half g_ath[BT_ * D_];                      // attn out hi (left only)
__device__ __half g_wqkv_h[E_ * D_], g_wqkv_l[E_ * D_];
__device__ __half g_wout_h[D_ * D_], g_wout_l[D_ * D_];

// ---------------------------------------------------------------------------
// helpers (fp16 split)
// ---------------------------------------------------------------------------
__device__ __forceinline__ unsigned pack2(float x, float y) {
    __half2 h = __floats2half2_rn(x, y);   // .x in low half
    return *(unsigned*)&h;
}
__device__ __forceinline__ float resid(float x) {
    return x - __half2float(__float2half_rn(x));
}
__device__ __forceinline__ void mma16816(float c[4], const unsigned a[4], const unsigned b[2]) {
    asm volatile(
        "mma.sync.aligned.m16n8k16.row.col.f32.f16.f16.f32 "
        "{%0,%1,%2,%3},{%4,%5,%6,%7},{%8,%9},{%0,%1,%2,%3};\n"
        : "+f"(c[0]), "+f"(c[1]), "+f"(c[2]), "+f"(c[3])
        : "r"(a[0]), "r"(a[1]), "r"(a[2]), "r"(a[3]), "r"(b[0]), "r"(b[1]));
}
__device__ __forceinline__ void cp16(void* dst_smem, const void* src) {
    unsigned d = (unsigned)__cvta_generic_to_shared(dst_smem);
    asm volatile("cp.async.cg.shared.global [%0], [%1], 16;\n" :: "r"(d), "l"(src));
}
__device__ __forceinline__ void cp_commit() { asm volatile("cp.async.commit_group;\n" ::: "memory"); }
__device__ __forceinline__ void cp_wait0()  { asm volatile("cp.async.wait_group 0;\n" ::: "memory"); }
__device__ __forceinline__ void cp_wait1()  { asm volatile("cp.async.wait_group 1;\n" ::: "memory"); }
__device__ __forceinline__ void ldmx4(unsigned r[4], const void* p) {
    unsigned a = (unsigned)__cvta_generic_to_shared(p);
    asm volatile("ldmatrix.sync.aligned.m8n8.x4.shared.b16 {%0,%1,%2,%3},[%4];\n"
                 : "=r"(r[0]), "=r"(r[1]), "=r"(r[2]), "=r"(r[3]) : "r"(a));
}
__device__ __forceinline__ void ldmx4t(unsigned r[4], const void* p) {
    unsigned a = (unsigned)__cvta_generic_to_shared(p);
    asm volatile("ldmatrix.sync.aligned.m8n8.x4.trans.shared.b16 {%0,%1,%2,%3},[%4];\n"
                 : "=r"(r[0]), "=r"(r[1]), "=r"(r[2]), "=r"(r[3]) : "r"(a));
}

// ---------------------------------------------------------------------------
// x split: fp32 -> fp16 hi (x is only ever a LEFT operand; lo never used)
// ---------------------------------------------------------------------------
__global__ void xsplit_kernel(const float* __restrict__ X, __half* __restrict__ Xh)
{
    long i = (long)(blockIdx.x * blockDim.x + threadIdx.x) * 4;
    if (i >= (long)BT_ * D_) return;
    float4 v = *(const float4*)(X + i);
    *(uint2*)(Xh + i) = make_uint2(pack2(v.x, v.y), pack2(v.z, v.w));
}

// ---------------------------------------------------------------------------
// Weight split+transpose: W[K][N] fp32 -> Wt_hi/Wt_lo [N][K] fp16
// ---------------------------------------------------------------------------
__global__ void wsplit_kernel(const float* __restrict__ W,
                              __half* __restrict__ Oh,
                              __half* __restrict__ Ol, int K, int N)
{
    __shared__ float t[32][33];
    int n0 = blockIdx.x * 32, k0 = blockIdx.y * 32;
    for (int i = threadIdx.y; i < 32; i += 8)
        t[i][threadIdx.x] = W[(long)(k0 + i) * N + n0 + threadIdx.x];
    __syncthreads();
    for (int i = threadIdx.y; i < 32; i += 8) {
        float v = t[threadIdx.x][i];
        long o = (long)(n0 + i) * K + k0 + threadIdx.x;
        __half h = __float2half_rn(v);
        Oh[o] = h;
        Ol[o] = __float2half_rn(v - __half2float(h));
    }
}

// ---------------------------------------------------------------------------
// GEMM (fp16x2, mma.sync): C[M,N] = A[M,K] * W[K,N]
// A hi-only [M][K]; W hi/lo transposed [N][K]. Per product: Ah*Bh + Ah*Bl.
// 128x128x32 tiles, 256 threads, warptile 32x64, XOR-swizzled rows,
// 3-stage cp.async ring @ 24 KB/stage -> 72 KB -> 2 CTAs/SM.
// mode 0: write C fp32.  mode 1: fused RoPE + fp16 hi/lo split -> Ch/Cl.
// ---------------------------------------------------------------------------
#define GMAT 8192                 // bytes per matrix tile (128 rows x 64 B)
#define GSTAGE (3 * GMAT)         // Ah,Bh,Bl = 24576 B
#define GEMM_SMEM (3 * GSTAGE)    // 73728 B

__global__ void __launch_bounds__(256, 2) gemm_fp16x2(
    const __half* __restrict__ Ah_g,
    const __half* __restrict__ Bh_g, const __half* __restrict__ Bl_g,
    float* __restrict__ C, int M, int N, int K, int mode,
    const float* __restrict__ sinb, const float* __restrict__ cosb,
    __half* __restrict__ Ch, __half* __restrict__ Cl)
{
    extern __shared__ __align__(128) char gsm[];
    const int tid = threadIdx.x, lane = tid & 31, warp = tid >> 5;
    const int row0 = blockIdx.y * 128, col0 = blockIdx.x * 128;
    const int m0 = (warp >> 1) * 32, n0w = (warp & 1) * 64;
    const int rw = lane >> 2, cw = lane & 3;
    const int nk = K >> 5;

    float acc[2][8][4];
#pragma unroll
    for (int mt = 0; mt < 2; mt++)
#pragma unroll
        for (int nt = 0; nt < 8; nt++)
#pragma unroll
            for (int e = 0; e < 4; e++) acc[mt][nt][e] = 0.f;

    auto issue = [&](int st, int kb) {
        char* base = gsm + st * GSTAGE;
#pragma unroll
        for (int l = 0; l < 6; l++) {
            int idx = tid + l * 256;               // 0..1535
            int mat = idx >> 9;                    // 0:Ah 1:Bh 2:Bl
            int r   = (idx >> 2) & 127;
            int c   = idx & 3;                     // logical 16B chunk
            const __half* g = (mat == 0) ? Ah_g : (mat == 1) ? Bh_g : Bl_g;
            long grow = (long)((mat == 0 ? row0 : col0) + r);
            cp16(base + mat * GMAT + r * 64 + ((c ^ ((r >> 1) & 3)) << 4),
                 g + grow * K + kb * 32 + c * 8);
        }
        cp_commit();
    };

    issue(0, 0);
    if (nk > 1) issue(1, 1);

    for (int kb = 0; kb < nk; kb++) {
        const int st = kb % 3;
        if (kb + 1 < nk) cp_wait1(); else cp_wait0();
        __syncthreads();
        if (kb + 2 < nk) issue((kb + 2) % 3, kb + 2);   // into stage free since last iter

        char* base = gsm + st * GSTAGE;
#pragma unroll
        for (int s = 0; s < 2; s++) {
            unsigned ah[2][4];
#pragma unroll
            for (int mt = 0; mt < 2; mt++) {
                int row = m0 + mt * 16 + (lane & 15);
                int ch  = 2 * s + (lane >> 4);
                ldmx4(ah[mt], base + row * 64 + ((ch ^ ((row >> 1) & 3)) << 4));
            }
#pragma unroll
            for (int ntp = 0; ntp < 4; ntp++) {
                int row = n0w + ntp * 16 + ((lane >> 4) << 3) + (lane & 7);
                int ch  = 2 * s + ((lane & 8) >> 3);
                int off = row * 64 + ((ch ^ ((row >> 1) & 3)) << 4);
                unsigned bh4[4], bl4[4];
                ldmx4(bh4, base + GMAT + off);
                ldmx4(bl4, base + 2 * GMAT + off);
                unsigned bh0[2] = { bh4[0], bh4[1] }, bl0[2] = { bl4[0], bl4[1] };
                unsigned bh1[2] = { bh4[2], bh4[3] }, bl1[2] = { bl4[2], bl4[3] };
#pragma unroll
                for (int mt = 0; mt < 2; mt++) {
                    mma16816(acc[mt][2 * ntp],     ah[mt], bh0);
                    mma16816(acc[mt][2 * ntp],     ah[mt], bl0);
                    mma16816(acc[mt][2 * ntp + 1], ah[mt], bh1);
                    mma16816(acc[mt][2 * ntp + 1], ah[mt], bl1);
                }
            }
        }
    }

    // ---- epilogue
    if (mode == 0) {
#pragma unroll
        for (int mt = 0; mt < 2; mt++) {
#pragma unroll
            for (int nt = 0; nt < 8; nt++) {
                int row = row0 + m0 + mt * 16 + rw;
                int col = col0 + n0w + nt * 8 + cw * 2;
                *(float2*)(C + (long)row * N + col)       = make_float2(acc[mt][nt][0], acc[mt][nt][1]);
                *(float2*)(C + (long)(row + 8) * N + col) = make_float2(acc[mt][nt][2], acc[mt][nt][3]);
            }
        }
    } else {
        const bool isv = (col0 + n0w) >= (D_ + KV_);
#pragma unroll
        for (int mt = 0; mt < 2; mt++) {
            int rbase = row0 + m0 + mt * 16 + rw;
#pragma unroll
            for (int half = 0; half < 2; half++) {
                int r = rbase + half * 8;
                int t = r & (T_ - 1);
                if (!isv) {
#pragma unroll
                    for (int nt = 0; nt < 4; nt++) {
                        float ol0[2], ol1[2];
#pragma unroll
                        for (int d = 0; d < 2; d++) {
                            int e = half * 2 + d;
                            float u1 = acc[mt][nt][e];
                            float u2 = acc[mt][nt + 4][e];
                            int i = nt * 8 + cw * 2 + d;
                            float c1 = cosb[t * HD_ + i],      s1 = sinb[t * HD_ + i];
                            float c2 = cosb[t * HD_ + i + 32], s2 = sinb[t * HD_ + i + 32];
                            ol0[d] = u1 * c1 - u2 * s1;
                            ol1[d] = u2 * c2 + u1 * s2;
                        }
                        long p = (long)r * E_ + col0 + n0w + nt * 8 + cw * 2;
                        *(unsigned*)(Ch + p)      = pack2(ol0[0], ol0[1]);
                        *(unsigned*)(Cl + p)      = pack2(resid(ol0[0]), resid(ol0[1]));
                        *(unsigned*)(Ch + p + 32) = pack2(ol1[0], ol1[1]);
                        *(unsigned*)(Cl + p + 32) = pack2(resid(ol1[0]), resid(ol1[1]));
                    }
                } else {
#pragma unroll
                    for (int nt = 0; nt < 8; nt++) {
                        float v0 = acc[mt][nt][half * 2];
                        float v1 = acc[mt][nt][half * 2 + 1];
                        long p = (long)r * E_ + col0 + n0w + nt * 8 + cw * 2;
                        *(unsigned*)(Ch + p) = pack2(v0, v1);
                        *(unsigned*)(Cl + p) = pack2(resid(v0), resid(v1));
                    }
                }
            }
        }
    }
}

// ---------------------------------------------------------------------------
// Flash attention (causal, GQA), mma.sync fp16x2. 256 threads (8 warps),
// q-tile 128 rows (16/warp). K/V tiles 64 rows, double-buffered cp.async.
// Q hi-only (left operand); K,V hi+lo (right). P hi-only.
// Smem: Q 16 KB + 2 stages x 32 KB = 80 KB -> 2 CTAs/SM.
// ---------------------------------------------------------------------------
#define AMAT_Q 16384              // 128 rows x 128 B
#define AMAT_KV 8192              // 64 rows x 128 B
#define ASTAGE (4 * AMAT_KV)      // Kh,Kl,Vh,Vl = 32768 B
#define ATTN_SMEM (AMAT_Q + 2 * ASTAGE)   // 81920 B

__global__ void __launch_bounds__(256, 2) attn_mma(
    const __half* __restrict__ qkvh, const __half* __restrict__ qkvl,
    __half* __restrict__ oh)
{
    extern __shared__ __align__(128) char asm_[];
    const int tid = threadIdx.x, lane = tid & 31, warp = tid >> 5;
    const int qb = blockIdx.x, h = blockIdx.y, b = blockIdx.z;
    const int q0 = qb * 128;
    const int rw = lane >> 2, cw = lane & 3;
    const int wrow0 = q0 + warp * 16;

    const long qbase = (long)(b * T_) * E_ + h * HD_;
    const long kbase = (long)(b * T_) * E_ + D_ + (h >> 2) * HD_;
    const long vbase = kbase + KV_;

    // issue Q hi (one cp.async group): 128 rows x 8 chunks = 1024
#pragma unroll
    for (int l = 0; l < 4; l++) {
        int idx = tid + l * 256;
        int r = (idx >> 3) & 127, c = idx & 7;
        cp16(asm_ + r * 128 + ((c ^ (r & 7)) << 4),
             qkvh + qbase + (long)(q0 + r) * E_ + c * 8);
    }
    cp_commit();

    const int njb = 2 * qb + 2;

    auto issueKV = [&](int jb, int st) {
        char* sb = asm_ + AMAT_Q + st * ASTAGE;
        const int k0 = jb * 64;
#pragma unroll
        for (int l = 0; l < 8; l++) {
            int idx = tid + l * 256;
            int mat = idx >> 9;                 // 0:Kh 1:Kl 2:Vh 3:Vl
            int r = (idx >> 3) & 63, c = idx & 7;
            const __half* gsrc = (mat & 1) ? qkvl : qkvh;
            long base = (mat >= 2) ? vbase : kbase;
            cp16(sb + mat * AMAT_KV + r * 128 + ((c ^ (r & 7)) << 4),
                 gsrc + base + (long)(k0 + r) * E_ + c * 8);
        }
        cp_commit();
    };

    issueKV(0, 0);
    issueKV(1, 1);

    float O[8][4];
#pragma unroll
    for (int nt = 0; nt < 8; nt++)
#pragma unroll
        for (int e = 0; e < 4; e++) O[nt][e] = 0.f;
    float m0v = -INFINITY, m1v = -INFINITY, l0v = 0.f, l1v = 0.f;

    for (int jb = 0; jb < njb; jb++) {
        const int st = jb & 1;
        const int k0 = jb * 64;
        if (jb + 1 < njb) cp_wait1(); else cp_wait0();
        __syncthreads();

        const bool active = (k0 <= wrow0 + 15);
        if (active) {
            char* sb = asm_ + AMAT_Q + st * ASTAGE;

            // S = Q K^T   (Qh*Kh + Qh*Kl)
            float S[8][4];
#pragma unroll
            for (int nt = 0; nt < 8; nt++)
#pragma unroll
                for (int e = 0; e < 4; e++) S[nt][e] = 0.f;

#pragma unroll
            for (int s = 0; s < 4; s++) {
                unsigned qh4[4];
                {
                    int row = warp * 16 + (lane & 15);
                    int ch  = 2 * s + (lane >> 4);
                    ldmx4(qh4, asm_ + row * 128 + ((ch ^ (row & 7)) << 4));
                }
#pragma unroll
                for (int ntp = 0; ntp < 4; ntp++) {
                    int row = ntp * 16 + ((lane >> 4) << 3) + (lane & 7);
                    int ch  = 2 * s + ((lane & 8) >> 3);
                    int off = row * 128 + ((ch ^ (row & 7)) << 4);
                    unsigned kh4[4], kl4[4];
                    ldmx4(kh4, sb + off);
                    ldmx4(kl4, sb + AMAT_KV + off);
                    unsigned kh0[2] = { kh4[0], kh4[1] }, kl0[2] = { kl4[0], kl4[1] };
                    unsigned kh1[2] = { kh4[2], kh4[3] }, kl1[2] = { kl4[2], kl4[3] };
                    mma16816(S[2 * ntp],     qh4, kh0);
                    mma16816(S[2 * ntp],     qh4, kl0);
                    mma16816(S[2 * ntp + 1], qh4, kh1);
                    mma16816(S[2 * ntp + 1], qh4, kl1);
                }
            }

            const float sc = 0.125f;
            if (k0 + 63 > wrow0) {      // diagonal tile for this warp
#pragma unroll
                for (int nt = 0; nt < 8; nt++)
#pragma unroll
                    for (int e = 0; e < 4; e++) {
                        int r = wrow0 + rw + ((e >= 2) ? 8 : 0);
                        int c = k0 + nt * 8 + cw * 2 + (e & 1);
                        S[nt][e] = (c <= r) ? S[nt][e] * sc : -1e30f;
                    }
            } else {
#pragma unroll
                for (int nt = 0; nt < 8; nt++)
#pragma unroll
                    for (int e = 0; e < 4; e++) S[nt][e] *= sc;
            }

            // online softmax
            float mx0 = -INFINITY, mx1 = -INFINITY;
#pragma unroll
            for (int nt = 0; nt < 8; nt++) {
                mx0 = fmaxf(mx0, fmaxf(S[nt][0], S[nt][1]));
                mx1 = fmaxf(mx1, fmaxf(S[nt][2], S[nt][3]));
            }
            mx0 = fmaxf(mx0, __shfl_xor_sync(0xffffffff, mx0, 1));
            mx0 = fmaxf(mx0, __shfl_xor_sync(0xffffffff, mx0, 2));
            mx1 = fmaxf(mx1, __shfl_xor_sync(0xffffffff, mx1, 1));
            mx1 = fmaxf(mx1, __shfl_xor_sync(0xffffffff, mx1, 2));
            float mn0 = fmaxf(m0v, mx0), mn1 = fmaxf(m1v, mx1);
            float a0 = exp2f((m0v - mn0) * LOG2E), a1 = exp2f((m1v - mn1) * LOG2E);
            m0v = mn0; m1v = mn1;
            float sum0 = 0.f, sum1 = 0.f;
#pragma unroll
            for (int nt = 0; nt < 8; nt++) {
                float p0 = exp2f((S[nt][0] - mn0) * LOG2E);
                float p1 = exp2f((S[nt][1] - mn0) * LOG2E);
                float p2 = exp2f((S[nt][2] - mn1) * LOG2E);
                float p3 = exp2f((S[nt][3] - mn1) * LOG2E);
                S[nt][0] = p0; S[nt][1] = p1; S[nt][2] = p2; S[nt][3] = p3;
                sum0 += p0 + p1; sum1 += p2 + p3;
            }
            sum0 += __shfl_xor_sync(0xffffffff, sum0, 1);
            sum0 += __shfl_xor_sync(0xffffffff, sum0, 2);
            sum1 += __shfl_xor_sync(0xffffffff, sum1, 1);
            sum1 += __shfl_xor_sync(0xffffffff, sum1, 2);
            l0v = l0v * a0 + sum0;
            l1v = l1v * a1 + sum1;
#pragma unroll
            for (int nt = 0; nt < 8; nt++) {
                O[nt][0] *= a0; O[nt][1] *= a0;
                O[nt][2] *= a1; O[nt][3] *= a1;
            }

            // O += P V   (Ph*Vh + Ph*Vl)
#pragma unroll
            for (int s = 0; s < 4; s++) {
                const int j0 = 2 * s, j1 = 2 * s + 1;
                unsigned ph_[4];
                ph_[0] = pack2(S[j0][0], S[j0][1]);
                ph_[1] = pack2(S[j0][2], S[j0][3]);
                ph_[2] = pack2(S[j1][0], S[j1][1]);
                ph_[3] = pack2(S[j1][2], S[j1][3]);
#pragma unroll
                for (int dt = 0; dt < 4; dt++) {
                    int vrow = s * 16 + (lane & 15);
                    int ch   = 2 * dt + (lane >> 4);
                    int off  = vrow * 128 + ((ch ^ (vrow & 7)) << 4);
                    unsigned vh4[4], vl4[4];
                    ldmx4t(vh4, sb + 2 * AMAT_KV + off);
                    ldmx4t(vl4, sb + 3 * AMAT_KV + off);
                    unsigned bh0[2] = { vh4[0], vh4[1] }, bl0[2] = { vl4[0], vl4[1] };
                    unsigned bh1[2] = { vh4[2], vh4[3] }, bl1[2] = { vl4[2], vl4[3] };
                    mma16816(O[2 * dt], ph_, bh0);
                    mma16816(O[2 * dt], ph_, bl0);
                    mma16816(O[2 * dt + 1], ph_, bh1);
                    mma16816(O[2 * dt + 1], ph_, bl1);
                }
            }
        }
        __syncthreads();
        if (jb + 2 < njb) issueKV(jb + 2, st);
    }

    // epilogue: normalize, write fp16 hi only (attn out is a LEFT operand)
    float i0 = 1.f / l0v, i1 = 1.f / l1v;
    long row = (long)(b * T_ + wrow0 + rw);
    long colb = h * HD_ + cw * 2;
#pragma unroll
    for (int nt = 0; nt < 8; nt++) {
        long p0 = row * D_ + colb + nt * 8;
        long p1 = (row + 8) * D_ + colb + nt * 8;
        *(unsigned*)(oh + p0) = pack2(O[nt][0] * i0, O[nt][1] * i0);
        *(unsigned*)(oh + p1) = pack2(O[nt][2] * i1, O[nt][3] * i1);
    }
}

// ---------------------------------------------------------------------------
// Launch
// ---------------------------------------------------------------------------
extern "C" void kernel_launch(void* const* d_in, const int* in_sizes, int n_in,
                              void* d_out, int out_size)
{
    const float* x     = (const float*)d_in[0];
    const float* sinb  = (const float*)d_in[1];
    const float* cosb  = (const float*)d_in[2];
    const float* w_qkv = (const float*)d_in[3];
    const float* w_out = (const float*)d_in[4];
    float* out = (float*)d_out;

    __half *xh, *qh, *ql, *ath, *wqh, *wql, *woh, *wol;
    cudaGetSymbolAddress((void**)&xh, g_xh);
    cudaGetSymbolAddress((void**)&qh, g_qkvh);
    cudaGetSymbolAddress((void**)&ql, g_qkvl);
    cudaGetSymbolAddress((void**)&ath, g_ath);
    cudaGetSymbolAddress((void**)&wqh, g_wqkv_h);
    cudaGetSymbolAddress((void**)&wql, g_wqkv_l);
    cudaGetSymbolAddress((void**)&woh, g_wout_h);
    cudaGetSymbolAddress((void**)&wol, g_wout_l);

    cudaFuncSetAttribute(gemm_fp16x2, cudaFuncAttributeMaxDynamicSharedMemorySize, GEMM_SMEM);
    cudaFuncSetAttribute(attn_mma, cudaFuncAttributeMaxDynamicSharedMemorySize, ATTN_SMEM);

    // 0) splits
    xsplit_kernel<<<(BT_ * D_ / 4 + 255) / 256, 256>>>(x, xh);
    wsplit_kernel<<<dim3(E_ / 32, D_ / 32), dim3(32, 8)>>>(w_qkv, wqh, wql, D_, E_);
    wsplit_kernel<<<dim3(D_ / 32, D_ / 32), dim3(32, 8)>>>(w_out, woh, wol, D_, D_);

    // 1) QKV projection with fused RoPE + split epilogue
    gemm_fp16x2<<<dim3(E_ / 128, BT_ / 128), 256, GEMM_SMEM>>>(
        xh, wqh, wql, nullptr, BT_, E_, D_, 1, sinb, cosb, qh, ql);

    // 2) Flash attention (q-tile 128)
    attn_mma<<<dim3(T_ / 128, NH_, B_), 256, ATTN_SMEM>>>(qh, ql, ath);

    // 3) Output projection (fp32 epilogue)
    gemm_fp16x2<<<dim3(D_ / 128, BT_ / 128), 256, GEMM_SMEM>>>(
        ath, woh, wol, out, BT_, D_, D_, 0, nullptr, nullptr, nullptr, nullptr);
}

// round 11
// speedup vs baseline: 4.9035x; 1.0114x over previous
#include <cuda_runtime.h>
#include <cuda_fp16.h>
#include <math.h>

// Problem constants
#define B_  2
#define T_  2048
#define D_  2048
#define E_  3072          // D + 2*KV_DIM
#define KV_ 512
#define HD_ 64
#define NH_ 32
#define BT_ 4096          // B*T

#define LOG2E 1.4426950408889634f

// Scratch (static __device__ arrays; allocation-free rule)
__device__ __half g_xh[BT_ * D_];                       // x hi (left operand only)
__device__ __half g_qkvh[BT_ * E_], g_qkvl[BT_ * E_];   // roped qkv hi/lo
__device__ __half g_ath[BT_ * D_];                      // attn out hi (left only)
__device__ __half g_wqkv_h[E_ * D_], g_wqkv_l[E_ * D_];
__device__ __half g_wout_h[D_ * D_], g_wout_l[D_ * D_];

// ---------------------------------------------------------------------------
// helpers (fp16 split)
// ---------------------------------------------------------------------------
__device__ __forceinline__ unsigned pack2(float x, float y) {
    __half2 h = __floats2half2_rn(x, y);   // .x in low half
    return *(unsigned*)&h;
}
__device__ __forceinline__ float resid(float x) {
    return x - __half2float(__float2half_rn(x));
}
__device__ __forceinline__ void mma16816(float c[4], const unsigned a[4], const unsigned b[2]) {
    asm volatile(
        "mma.sync.aligned.m16n8k16.row.col.f32.f16.f16.f32 "
        "{%0,%1,%2,%3},{%4,%5,%6,%7},{%8,%9},{%0,%1,%2,%3};\n"
        : "+f"(c[0]), "+f"(c[1]), "+f"(c[2]), "+f"(c[3])
        : "r"(a[0]), "r"(a[1]), "r"(a[2]), "r"(a[3]), "r"(b[0]), "r"(b[1]));
}
__device__ __forceinline__ void cp16(void* dst_smem, const void* src) {
    unsigned d = (unsigned)__cvta_generic_to_shared(dst_smem);
    asm volatile("cp.async.cg.shared.global [%0], [%1], 16;\n" :: "r"(d), "l"(src));
}
__device__ __forceinline__ void cp_commit() { asm volatile("cp.async.commit_group;\n" ::: "memory"); }
__device__ __forceinline__ void cp_wait0()  { asm volatile("cp.async.wait_group 0;\n" ::: "memory"); }
__device__ __forceinline__ void cp_wait1()  { asm volatile("cp.async.wait_group 1;\n" ::: "memory"); }
__device__ __forceinline__ void cp_wait2()  { asm volatile("cp.async.wait_group 2;\n" ::: "memory"); }
__device__ __forceinline__ void ldmx4(unsigned r[4], const void* p) {
    unsigned a = (unsigned)__cvta_generic_to_shared(p);
    asm volatile("ldmatrix.sync.aligned.m8n8.x4.shared.b16 {%0,%1,%2,%3},[%4];\n"
                 : "=r"(r[0]), "=r"(r[1]), "=r"(r[2]), "=r"(r[3]) : "r"(a));
}
__device__ __forceinline__ void ldmx4t(unsigned r[4], const void* p) {
    unsigned a = (unsigned)__cvta_generic_to_shared(p);
    asm volatile("ldmatrix.sync.aligned.m8n8.x4.trans.shared.b16 {%0,%1,%2,%3},[%4];\n"
                 : "=r"(r[0]), "=r"(r[1]), "=r"(r[2]), "=r"(r[3]) : "r"(a));
}

// ---------------------------------------------------------------------------
// x split: fp32 -> fp16 hi (x is only ever a LEFT operand; lo never used)
// ---------------------------------------------------------------------------
__global__ void xsplit_kernel(const float* __restrict__ X, __half* __restrict__ Xh)
{
    long i = (long)(blockIdx.x * blockDim.x + threadIdx.x) * 4;
    if (i >= (long)BT_ * D_) return;
    float4 v = *(const float4*)(X + i);
    *(uint2*)(Xh + i) = make_uint2(pack2(v.x, v.y), pack2(v.z, v.w));
}

// ---------------------------------------------------------------------------
// Weight split+transpose: W[K][N] fp32 -> Wt_hi/Wt_lo [N][K] fp16
// ---------------------------------------------------------------------------
__global__ void wsplit_kernel(const float* __restrict__ W,
                              __half* __restrict__ Oh,
                              __half* __restrict__ Ol, int K, int N)
{
    __shared__ float t[32][33];
    int n0 = blockIdx.x * 32, k0 = blockIdx.y * 32;
    for (int i = threadIdx.y; i < 32; i += 8)
        t[i][threadIdx.x] = W[(long)(k0 + i) * N + n0 + threadIdx.x];
    __syncthreads();
    for (int i = threadIdx.y; i < 32; i += 8) {
        float v = t[threadIdx.x][i];
        long o = (long)(n0 + i) * K + k0 + threadIdx.x;
        __half h = __float2half_rn(v);
        Oh[o] = h;
        Ol[o] = __float2half_rn(v - __half2float(h));
    }
}

// ---------------------------------------------------------------------------
// GEMM (fp16x2, mma.sync): C[M,N] = A[M,K] * W[K,N]
// A hi-only [M][K]; W hi/lo transposed [N][K]. Per product: Ah*Bh + Ah*Bl.
// 128x128x32 tiles, 256 threads, warptile 32x64, XOR-swizzled rows,
// 4-stage cp.async ring @ 24 KB/stage -> 96 KB -> 2 CTAs/SM,
// prefetch depth 3, wait_group 2 (two k-blocks always in flight).
// mode 0: write C fp32.  mode 1: fused RoPE + fp16 hi/lo split -> Ch/Cl.
// ---------------------------------------------------------------------------
#define GMAT 8192                 // bytes per matrix tile (128 rows x 64 B)
#define GSTAGE (3 * GMAT)         // Ah,Bh,Bl = 24576 B
#define GEMM_SMEM (4 * GSTAGE)    // 98304 B

__global__ void __launch_bounds__(256, 2) gemm_fp16x2(
    const __half* __restrict__ Ah_g,
    const __half* __restrict__ Bh_g, const __half* __restrict__ Bl_g,
    float* __restrict__ C, int M, int N, int K, int mode,
    const float* __restrict__ sinb, const float* __restrict__ cosb,
    __half* __restrict__ Ch, __half* __restrict__ Cl)
{
    extern __shared__ __align__(128) char gsm[];
    const int tid = threadIdx.x, lane = tid & 31, warp = tid >> 5;
    const int row0 = blockIdx.y * 128, col0 = blockIdx.x * 128;
    const int m0 = (warp >> 1) * 32, n0w = (warp & 1) * 64;
    const int rw = lane >> 2, cw = lane & 3;
    const int nk = K >> 5;

    float acc[2][8][4];
#pragma unroll
    for (int mt = 0; mt < 2; mt++)
#pragma unroll
        for (int nt = 0; nt < 8; nt++)
#pragma unroll
            for (int e = 0; e < 4; e++) acc[mt][nt][e] = 0.f;

    auto issue = [&](int st, int kb) {
        char* base = gsm + st * GSTAGE;
#pragma unroll
        for (int l = 0; l < 6; l++) {
            int idx = tid + l * 256;               // 0..1535
            int mat = idx >> 9;                    // 0:Ah 1:Bh 2:Bl
            int r   = (idx >> 2) & 127;
            int c   = idx & 3;                     // logical 16B chunk
            const __half* g = (mat == 0) ? Ah_g : (mat == 1) ? Bh_g : Bl_g;
            long grow = (long)((mat == 0 ? row0 : col0) + r);
            cp16(base + mat * GMAT + r * 64 + ((c ^ ((r >> 1) & 3)) << 4),
                 g + grow * K + kb * 32 + c * 8);
        }
        cp_commit();
    };

    issue(0, 0);
    if (nk > 1) issue(1, 1);
    if (nk > 2) issue(2, 2);

    for (int kb = 0; kb < nk; kb++) {
        const int st = kb & 3;
        // ensure group kb is complete; groups kb+1, kb+2 may stay in flight
        if (kb + 2 < nk)      cp_wait2();
        else if (kb + 1 < nk) cp_wait1();
        else                  cp_wait0();
        __syncthreads();
        if (kb + 3 < nk) issue((kb + 3) & 3, kb + 3);   // stage freed at iter kb-1

        char* base = gsm + st * GSTAGE;
#pragma unroll
        for (int s = 0; s < 2; s++) {
            unsigned ah[2][4];
#pragma unroll
            for (int mt = 0; mt < 2; mt++) {
                int row = m0 + mt * 16 + (lane & 15);
                int ch  = 2 * s + (lane >> 4);
                ldmx4(ah[mt], base + row * 64 + ((ch ^ ((row >> 1) & 3)) << 4));
            }
#pragma unroll
            for (int ntp = 0; ntp < 4; ntp++) {
                int row = n0w + ntp * 16 + ((lane >> 4) << 3) + (lane & 7);
                int ch  = 2 * s + ((lane & 8) >> 3);
                int off = row * 64 + ((ch ^ ((row >> 1) & 3)) << 4);
                unsigned bh4[4], bl4[4];
                ldmx4(bh4, base + GMAT + off);
                ldmx4(bl4, base + 2 * GMAT + off);
                unsigned bh0[2] = { bh4[0], bh4[1] }, bl0[2] = { bl4[0], bl4[1] };
                unsigned bh1[2] = { bh4[2], bh4[3] }, bl1[2] = { bl4[2], bl4[3] };
#pragma unroll
                for (int mt = 0; mt < 2; mt++) {
                    mma16816(acc[mt][2 * ntp],     ah[mt], bh0);
                    mma16816(acc[mt][2 * ntp],     ah[mt], bl0);
                    mma16816(acc[mt][2 * ntp + 1], ah[mt], bh1);
                    mma16816(acc[mt][2 * ntp + 1], ah[mt], bl1);
                }
            }
        }
    }

    // ---- epilogue
    if (mode == 0) {
#pragma unroll
        for (int mt = 0; mt < 2; mt++) {
#pragma unroll
            for (int nt = 0; nt < 8; nt++) {
                int row = row0 + m0 + mt * 16 + rw;
                int col = col0 + n0w + nt * 8 + cw * 2;
                *(float2*)(C + (long)row * N + col)       = make_float2(acc[mt][nt][0], acc[mt][nt][1]);
                *(float2*)(C + (long)(row + 8) * N + col) = make_float2(acc[mt][nt][2], acc[mt][nt][3]);
            }
        }
    } else {
        const bool isv = (col0 + n0w) >= (D_ + KV_);
#pragma unroll
        for (int mt = 0; mt < 2; mt++) {
            int rbase = row0 + m0 + mt * 16 + rw;
#pragma unroll
            for (int half = 0; half < 2; half++) {
                int r = rbase + half * 8;
                int t = r & (T_ - 1);
                if (!isv) {
#pragma unroll
                    for (int nt = 0; nt < 4; nt++) {
                        float ol0[2], ol1[2];
#pragma unroll
                        for (int d = 0; d < 2; d++) {
                            int e = half * 2 + d;
                            float u1 = acc[mt][nt][e];
                            float u2 = acc[mt][nt + 4][e];
                            int i = nt * 8 + cw * 2 + d;
                            float c1 = cosb[t * HD_ + i],      s1 = sinb[t * HD_ + i];
                            float c2 = cosb[t * HD_ + i + 32], s2 = sinb[t * HD_ + i + 32];
                            ol0[d] = u1 * c1 - u2 * s1;
                            ol1[d] = u2 * c2 + u1 * s2;
                        }
                        long p = (long)r * E_ + col0 + n0w + nt * 8 + cw * 2;
                        *(unsigned*)(Ch + p)      = pack2(ol0[0], ol0[1]);
                        *(unsigned*)(Cl + p)      = pack2(resid(ol0[0]), resid(ol0[1]));
                        *(unsigned*)(Ch + p + 32) = pack2(ol1[0], ol1[1]);
                        *(unsigned*)(Cl + p + 32) = pack2(resid(ol1[0]), resid(ol1[1]));
                    }
                } else {
#pragma unroll
                    for (int nt = 0; nt < 8; nt++) {
                        float v0 = acc[mt][nt][half * 2];
                        float v1 = acc[mt][nt][half * 2 + 1];
                        long p = (long)r * E_ + col0 + n0w + nt * 8 + cw * 2;
                        *(unsigned*)(Ch + p) = pack2(v0, v1);
                        *(unsigned*)(Cl + p) = pack2(resid(v0), resid(v1));
                    }
                }
            }
        }
    }
}

// ---------------------------------------------------------------------------
// Flash attention (causal, GQA), mma.sync fp16x2. 256 threads (8 warps),
// q-tile 128 rows (16/warp). K/V tiles 64 rows, double-buffered cp.async.
// Q hi-only (left operand); K,V hi+lo (right). P hi-only.
// Smem: Q 16 KB + 2 stages x 32 KB = 80 KB -> 2 CTAs/SM.
// Largest-first scheduling: qb reversed vs blockIdx.x so long (high-qb)
// tiles launch in the first wave and short ones fill the tail.
// ---------------------------------------------------------------------------
#define AMAT_Q 16384              // 128 rows x 128 B
#define AMAT_KV 8192              // 64 rows x 128 B
#define ASTAGE (4 * AMAT_KV)      // Kh,Kl,Vh,Vl = 32768 B
#define ATTN_SMEM (AMAT_Q + 2 * ASTAGE)   // 81920 B

__global__ void __launch_bounds__(256, 2) attn_mma(
    const __half* __restrict__ qkvh, const __half* __restrict__ qkvl,
    __half* __restrict__ oh)
{
    extern __shared__ __align__(128) char asm_[];
    const int tid = threadIdx.x, lane = tid & 31, warp = tid >> 5;
    const int qb = gridDim.x - 1 - blockIdx.x;      // largest-first
    const int h = blockIdx.y, b = blockIdx.z;
    const int q0 = qb * 128;
    const int rw = lane >> 2, cw = lane & 3;
    const int wrow0 = q0 + warp * 16;

    const long qbase = (long)(b * T_) * E_ + h * HD_;
    const long kbase = (long)(b * T_) * E_ + D_ + (h >> 2) * HD_;
    const long vbase = kbase + KV_;

    // issue Q hi (one cp.async group): 128 rows x 8 chunks = 1024
#pragma unroll
    for (int l = 0; l < 4; l++) {
        int idx = tid + l * 256;
        int r = (idx >> 3) & 127, c = idx & 7;
        cp16(asm_ + r * 128 + ((c ^ (r & 7)) << 4),
             qkvh + qbase + (long)(q0 + r) * E_ + c * 8);
    }
    cp_commit();

    const int njb = 2 * qb + 2;

    auto issueKV = [&](int jb, int st) {
        char* sb = asm_ + AMAT_Q + st * ASTAGE;
        const int k0 = jb * 64;
#pragma unroll
        for (int l = 0; l < 8; l++) {
            int idx = tid + l * 256;
            int mat = idx >> 9;                 // 0:Kh 1:Kl 2:Vh 3:Vl
            int r = (idx >> 3) & 63, c = idx & 7;
            const __half* gsrc = (mat & 1) ? qkvl : qkvh;
            long base = (mat >= 2) ? vbase : kbase;
            cp16(sb + mat * AMAT_KV + r * 128 + ((c ^ (r & 7)) << 4),
                 gsrc + base + (long)(k0 + r) * E_ + c * 8);
        }
        cp_commit();
    };

    issueKV(0, 0);
    issueKV(1, 1);

    float O[8][4];
#pragma unroll
    for (int nt = 0; nt < 8; nt++)
#pragma unroll
        for (int e = 0; e < 4; e++) O[nt][e] = 0.f;
    float m0v = -INFINITY, m1v = -INFINITY, l0v = 0.f, l1v = 0.f;

    for (int jb = 0; jb < njb; jb++) {
        const int st = jb & 1;
        const int k0 = jb * 64;
        if (jb + 1 < njb) cp_wait1(); else cp_wait0();
        __syncthreads();

        const bool active = (k0 <= wrow0 + 15);
        if (active) {
            char* sb = asm_ + AMAT_Q + st * ASTAGE;

            // S = Q K^T   (Qh*Kh + Qh*Kl)
            float S[8][4];
#pragma unroll
            for (int nt = 0; nt < 8; nt++)
#pragma unroll
                for (int e = 0; e < 4; e++) S[nt][e] = 0.f;

#pragma unroll
            for (int s = 0; s < 4; s++) {
                unsigned qh4[4];
                {
                    int row = warp * 16 + (lane & 15);
                    int ch  = 2 * s + (lane >> 4);
                    ldmx4(qh4, asm_ + row * 128 + ((ch ^ (row & 7)) << 4));
                }
#pragma unroll
                for (int ntp = 0; ntp < 4; ntp++) {
                    int row = ntp * 16 + ((lane >> 4) << 3) + (lane & 7);
                    int ch  = 2 * s + ((lane & 8) >> 3);
                    int off = row * 128 + ((ch ^ (row & 7)) << 4);
                    unsigned kh4[4], kl4[4];
                    ldmx4(kh4, sb + off);
                    ldmx4(kl4, sb + AMAT_KV + off);
                    unsigned kh0[2] = { kh4[0], kh4[1] }, kl0[2] = { kl4[0], kl4[1] };
                    unsigned kh1[2] = { kh4[2], kh4[3] }, kl1[2] = { kl4[2], kl4[3] };
                    mma16816(S[2 * ntp],     qh4, kh0);
                    mma16816(S[2 * ntp],     qh4, kl0);
                    mma16816(S[2 * ntp + 1], qh4, kh1);
                    mma16816(S[2 * ntp + 1], qh4, kl1);
                }
            }

            const float sc = 0.125f;
            if (k0 + 63 > wrow0) {      // diagonal tile for this warp
#pragma unroll
                for (int nt = 0; nt < 8; nt++)
#pragma unroll
                    for (int e = 0; e < 4; e++) {
                        int r = wrow0 + rw + ((e >= 2) ? 8 : 0);
                        int c = k0 + nt * 8 + cw * 2 + (e & 1);
                        S[nt][e] = (c <= r) ? S[nt][e] * sc : -1e30f;
                    }
            } else {
#pragma unroll
                for (int nt = 0; nt < 8; nt++)
#pragma unroll
                    for (int e = 0; e < 4; e++) S[nt][e] *= sc;
            }

            // online softmax
            float mx0 = -INFINITY, mx1 = -INFINITY;
#pragma unroll
            for (int nt = 0; nt < 8; nt++) {
                mx0 = fmaxf(mx0, fmaxf(S[nt][0], S[nt][1]));
                mx1 = fmaxf(mx1, fmaxf(S[nt][2], S[nt][3]));
            }
            mx0 = fmaxf(mx0, __shfl_xor_sync(0xffffffff, mx0, 1));
            mx0 = fmaxf(mx0, __shfl_xor_sync(0xffffffff, mx0, 2));
            mx1 = fmaxf(mx1, __shfl_xor_sync(0xffffffff, mx1, 1));
            mx1 = fmaxf(mx1, __shfl_xor_sync(0xffffffff, mx1, 2));
            float mn0 = fmaxf(m0v, mx0), mn1 = fmaxf(m1v, mx1);
            float a0 = exp2f((m0v - mn0) * LOG2E), a1 = exp2f((m1v - mn1) * LOG2E);
            m0v = mn0; m1v = mn1;
            float sum0 = 0.f, sum1 = 0.f;
#pragma unroll
            for (int nt = 0; nt < 8; nt++) {
                float p0 = exp2f((S[nt][0] - mn0) * LOG2E);
                float p1 = exp2f((S[nt][1] - mn0) * LOG2E);
                float p2 = exp2f((S[nt][2] - mn1) * LOG2E);
                float p3 = exp2f((S[nt][3] - mn1) * LOG2E);
                S[nt][0] = p0; S[nt][1] = p1; S[nt][2] = p2; S[nt][3] = p3;
                sum0 += p0 + p1; sum1 += p2 + p3;
            }
            sum0 += __shfl_xor_sync(0xffffffff, sum0, 1);
            sum0 += __shfl_xor_sync(0xffffffff, sum0, 2);
            sum1 += __shfl_xor_sync(0xffffffff, sum1, 1);
            sum1 += __shfl_xor_sync(0xffffffff, sum1, 2);
            l0v = l0v * a0 + sum0;
            l1v = l1v * a1 + sum1;
#pragma unroll
            for (int nt = 0; nt < 8; nt++) {
                O[nt][0] *= a0; O[nt][1] *= a0;
                O[nt][2] *= a1; O[nt][3] *= a1;
            }

            // O += P V   (Ph*Vh + Ph*Vl)
#pragma unroll
            for (int s = 0; s < 4; s++) {
                const int j0 = 2 * s, j1 = 2 * s + 1;
                unsigned ph_[4];
                ph_[0] = pack2(S[j0][0], S[j0][1]);
                ph_[1] = pack2(S[j0][2], S[j0][3]);
                ph_[2] = pack2(S[j1][0], S[j1][1]);
                ph_[3] = pack2(S[j1][2], S[j1][3]);
#pragma unroll
                for (int dt = 0; dt < 4; dt++) {
                    int vrow = s * 16 + (lane & 15);
                    int ch   = 2 * dt + (lane >> 4);
                    int off  = vrow * 128 + ((ch ^ (vrow & 7)) << 4);
                    unsigned vh4[4], vl4[4];
                    ldmx4t(vh4, sb + 2 * AMAT_KV + off);
                    ldmx4t(vl4, sb + 3 * AMAT_KV + off);
                    unsigned bh0[2] = { vh4[0], vh4[1] }, bl0[2] = { vl4[0], vl4[1] };
                    unsigned bh1[2] = { vh4[2], vh4[3] }, bl1[2] = { vl4[2], vl4[3] };
                    mma16816(O[2 * dt], ph_, bh0);
                    mma16816(O[2 * dt], ph_, bl0);
                    mma16816(O[2 * dt + 1], ph_, bh1);
                    mma16816(O[2 * dt + 1], ph_, bl1);
                }
            }
        }
        __syncthreads();
        if (jb + 2 < njb) issueKV(jb + 2, st);
    }

    // epilogue: normalize, write fp16 hi only (attn out is a LEFT operand)
    float i0 = 1.f / l0v, i1 = 1.f / l1v;
    long row = (long)(b * T_ + wrow0 + rw);
    long colb = h * HD_ + cw * 2;
#pragma unroll
    for (int nt = 0; nt < 8; nt++) {
        long p0 = row * D_ + colb + nt * 8;
        long p1 = (row + 8) * D_ + colb + nt * 8;
        *(unsigned*)(oh + p0) = pack2(O[nt][0] * i0, O[nt][1] * i0);
        *(unsigned*)(oh + p1) = pack2(O[nt][2] * i1, O[nt][3] * i1);
    }
}

// ---------------------------------------------------------------------------
// Launch
// ---------------------------------------------------------------------------
extern "C" void kernel_launch(void* const* d_in, const int* in_sizes, int n_in,
                              void* d_out, int out_size)
{
    const float* x     = (const float*)d_in[0];
    const float* sinb  = (const float*)d_in[1];
    const float* cosb  = (const float*)d_in[2];
    const float* w_qkv = (const float*)d_in[3];
    const float* w_out = (const float*)d_in[4];
    float* out = (float*)d_out;

    __half *xh, *qh, *ql, *ath, *wqh, *wql, *woh, *wol;
    cudaGetSymbolAddress((void**)&xh, g_xh);
    cudaGetSymbolAddress((void**)&qh, g_qkvh);
    cudaGetSymbolAddress((void**)&ql, g_qkvl);
    cudaGetSymbolAddress((void**)&ath, g_ath);
    cudaGetSymbolAddress((void**)&wqh, g_wqkv_h);
    cudaGetSymbolAddress((void**)&wql, g_wqkv_l);
    cudaGetSymbolAddress((void**)&woh, g_wout_h);
    cudaGetSymbolAddress((void**)&wol, g_wout_l);

    cudaFuncSetAttribute(gemm_fp16x2, cudaFuncAttributeMaxDynamicSharedMemorySize, GEMM_SMEM);
    cudaFuncSetAttribute(attn_mma, cudaFuncAttributeMaxDynamicSharedMemorySize, ATTN_SMEM);

    // 0) splits
    xsplit_kernel<<<(BT_ * D_ / 4 + 255) / 256, 256>>>(x, xh);
    wsplit_kernel<<<dim3(E_ / 32, D_ / 32), dim3(32, 8)>>>(w_qkv, wqh, wql, D_, E_);
    wsplit_kernel<<<dim3(D_ / 32, D_ / 32), dim3(32, 8)>>>(w_out, woh, wol, D_, D_);

    // 1) QKV projection with fused RoPE + split epilogue
    gemm_fp16x2<<<dim3(E_ / 128, BT_ / 128), 256, GEMM_SMEM>>>(
        xh, wqh, wql, nullptr, BT_, E_, D_, 1, sinb, cosb, qh, ql);

    // 2) Flash attention (q-tile 128, largest-first)
    attn_mma<<<dim3(T_ / 128, NH_, B_), 256, ATTN_SMEM>>>(qh, ql, ath);

    // 3) Output projection (fp32 epilogue)
    gemm_fp16x2<<<dim3(D_ / 128, BT_ / 128), 256, GEMM_SMEM>>>(
        ath, woh, wol, out, BT_, D_, D_, 0, nullptr, nullptr, nullptr, nullptr);
}